// round 2
// baseline (speedup 1.0000x reference)
#include <cuda_runtime.h>

#define N_NODES 200000
#define NB 3125            // N_NODES / 64
#define EPS_BN 1e-3f

typedef unsigned long long ull;

// ---------------- scratch (device globals; no allocations allowed) ----------
__device__ float g_y1[N_NODES * 64];    // x @ W1 (pre-BN)
__device__ float g_y2[N_NODES * 64];    // gathered conv output (pre-BN)
__device__ float g_z [N_NODES * 256];   // h2 @ W3 (pre-BN)
__device__ float g_part1[NB * 128];     // per-block [sum(64) | sumsq(64)]
__device__ float g_part2[NB * 128];
__device__ float g_part3[NB * 512];     // per-block [sum(256) | sumsq(256)]
__device__ float g_sc1[64],  g_sh1[64];
__device__ float g_sc2[64],  g_sh2[64];
__device__ float g_sc3[256], g_sh3[256];

// ---------------- packed f32x2 helpers (FFMA2 path, sm_103a) ----------------
__device__ __forceinline__ ull pack2(float x) {
    ull r; asm("mov.b64 %0, {%1, %1};" : "=l"(r) : "f"(x)); return r;
}
__device__ __forceinline__ void fma2(ull& d, ull a, ull b) {
    asm("fma.rn.f32x2 %0, %1, %2, %0;" : "+l"(d) : "l"(a), "l"(b));
}
__device__ __forceinline__ float2 unpk(ull v) {
    float2 r; asm("mov.b64 {%0, %1}, %2;" : "=f"(r.x), "=f"(r.y) : "l"(v)); return r;
}

// ---------------- shared epilogue: store tile + per-block BN stat partials --
// acc[i][j] holds rows {ty+16i}, col-pairs {2*(tx+8j), 2*(tx+8j)+1} (local).
// red: 16*64 floats of reusable smem. psum_out/psq_out: 64 floats each.
__device__ __forceinline__ void epilogue_store_stats(
    ull acc[4][4], float* ybuf, int ypitch, int row0, int col0,
    float* red, float* psum_out, float* psq_out, int tx, int ty, int tid)
{
    float ps[8], pq[8];
#pragma unroll
    for (int u = 0; u < 8; u++) { ps[u] = 0.f; pq[u] = 0.f; }
#pragma unroll
    for (int i = 0; i < 4; i++) {
        int row = row0 + ty + 16 * i;
#pragma unroll
        for (int j = 0; j < 4; j++) {
            float2 v = unpk(acc[i][j]);
            *(float2*)&ybuf[(size_t)row * ypitch + col0 + 2 * (tx + 8 * j)] = v;
            ps[2 * j]     += v.x;  pq[2 * j]     += v.x * v.x;
            ps[2 * j + 1] += v.y;  pq[2 * j + 1] += v.y * v.y;
        }
    }
    __syncthreads();   // everyone done computing; smem safe to reuse
#pragma unroll
    for (int j = 0; j < 4; j++) {
        red[ty * 64 + 2 * (tx + 8 * j)]     = ps[2 * j];
        red[ty * 64 + 2 * (tx + 8 * j) + 1] = ps[2 * j + 1];
    }
    __syncthreads();
    if (tid < 64) {
        float s = 0.f;
#pragma unroll
        for (int t = 0; t < 16; t++) s += red[t * 64 + tid];
        psum_out[tid] = s;
    }
    __syncthreads();
#pragma unroll
    for (int j = 0; j < 4; j++) {
        red[ty * 64 + 2 * (tx + 8 * j)]     = pq[2 * j];
        red[ty * 64 + 2 * (tx + 8 * j) + 1] = pq[2 * j + 1];
    }
    __syncthreads();
    if (tid < 64) {
        float s = 0.f;
#pragma unroll
        for (int t = 0; t < 16; t++) s += red[t * 64 + tid];
        psq_out[tid] = s;
    }
}

// ---------------- K1: y1 = x @ W1  ([N,256] x [256,64]) + stats ------------
__global__ __launch_bounds__(128) void k1_gemm(
    const float* __restrict__ x, const float* __restrict__ W1)
{
    __shared__ __align__(16) float x_s[64 * 32];
    __shared__ __align__(16) float w_s[32 * 64];
    int tid = threadIdx.x, tx = tid & 7, ty = tid >> 3;
    int bid = blockIdx.x, row0 = bid * 64;

    ull acc[4][4];
#pragma unroll
    for (int i = 0; i < 4; i++)
#pragma unroll
        for (int j = 0; j < 4; j++) acc[i][j] = 0ull;

    for (int kk = 0; kk < 256; kk += 32) {
#pragma unroll
        for (int q = 0; q < 4; q++) {
            int fi = tid + q * 128; int r = fi >> 3, c4 = fi & 7;
            *(float4*)&x_s[r * 32 + c4 * 4] =
                *(const float4*)&x[(size_t)(row0 + r) * 256 + kk + c4 * 4];
        }
#pragma unroll
        for (int q = 0; q < 4; q++) {
            int fi = tid + q * 128; int r = fi >> 4, c4 = fi & 15;
            *(float4*)&w_s[r * 64 + c4 * 4] =
                *(const float4*)&W1[(size_t)(kk + r) * 64 + c4 * 4];
        }
        __syncthreads();
#pragma unroll
        for (int c = 0; c < 32; c++) {
            ull av0 = pack2(x_s[ ty       * 32 + c]);
            ull av1 = pack2(x_s[(ty + 16) * 32 + c]);
            ull av2 = pack2(x_s[(ty + 32) * 32 + c]);
            ull av3 = pack2(x_s[(ty + 48) * 32 + c]);
#pragma unroll
            for (int j = 0; j < 4; j++) {
                ull wv = *(const ull*)&w_s[c * 64 + 2 * (tx + 8 * j)];
                fma2(acc[0][j], av0, wv);
                fma2(acc[1][j], av1, wv);
                fma2(acc[2][j], av2, wv);
                fma2(acc[3][j], av3, wv);
            }
        }
        __syncthreads();
    }
    epilogue_store_stats(acc, g_y1, 64, row0, 0, x_s,
                         g_part1 + bid * 128, g_part1 + bid * 128 + 64,
                         tx, ty, tid);
}

// ---------------- K2: y2[n] = sum_k relu(bn1(y1[neigh[n,k]])) @ W2[k] ------
__global__ __launch_bounds__(128) void k2_gather(
    const int* __restrict__ neigh, const float* __restrict__ W2)
{
    __shared__ __align__(16) float a_s[64 * 64];
    __shared__ __align__(16) float w_s[64 * 64];
    __shared__ int   s_idx[64 * 27];
    __shared__ float s_sc[64], s_sh[64];
    int tid = threadIdx.x, tx = tid & 7, ty = tid >> 3;
    int bid = blockIdx.x, row0 = bid * 64;

    if (tid < 64) { s_sc[tid] = g_sc1[tid]; s_sh[tid] = g_sh1[tid]; }
    for (int i = tid; i < 64 * 27; i += 128)
        s_idx[i] = neigh[(size_t)row0 * 27 + i];
    __syncthreads();

    ull acc[4][4];
#pragma unroll
    for (int i = 0; i < 4; i++)
#pragma unroll
        for (int j = 0; j < 4; j++) acc[i][j] = 0ull;

    for (int k = 0; k < 27; k++) {
#pragma unroll
        for (int q = 0; q < 8; q++) {
            int fi = tid + q * 128; int c = fi >> 4, d4 = fi & 15;
            *(float4*)&w_s[c * 64 + d4 * 4] =
                *(const float4*)&W2[(size_t)k * 4096 + c * 64 + d4 * 4];
        }
#pragma unroll
        for (int q = 0; q < 8; q++) {
            int fi = tid + q * 128; int r = fi >> 4, c4 = fi & 15; int c0 = c4 * 4;
            int g = s_idx[r * 27 + k];
            float4 v = *(const float4*)&g_y1[(size_t)g * 64 + c0];
            v.x = fmaxf(fmaf(v.x, s_sc[c0],     s_sh[c0]),     0.f);
            v.y = fmaxf(fmaf(v.y, s_sc[c0 + 1], s_sh[c0 + 1]), 0.f);
            v.z = fmaxf(fmaf(v.z, s_sc[c0 + 2], s_sh[c0 + 2]), 0.f);
            v.w = fmaxf(fmaf(v.w, s_sc[c0 + 3], s_sh[c0 + 3]), 0.f);
            *(float4*)&a_s[r * 64 + c0] = v;
        }
        __syncthreads();
#pragma unroll 8
        for (int c = 0; c < 64; c++) {
            ull av0 = pack2(a_s[ ty       * 64 + c]);
            ull av1 = pack2(a_s[(ty + 16) * 64 + c]);
            ull av2 = pack2(a_s[(ty + 32) * 64 + c]);
            ull av3 = pack2(a_s[(ty + 48) * 64 + c]);
#pragma unroll
            for (int j = 0; j < 4; j++) {
                ull wv = *(const ull*)&w_s[c * 64 + 2 * (tx + 8 * j)];
                fma2(acc[0][j], av0, wv);
                fma2(acc[1][j], av1, wv);
                fma2(acc[2][j], av2, wv);
                fma2(acc[3][j], av3, wv);
            }
        }
        __syncthreads();
    }
    epilogue_store_stats(acc, g_y2, 64, row0, 0, a_s,
                         g_part2 + bid * 128, g_part2 + bid * 128 + 64,
                         tx, ty, tid);
}

// ---------------- K3: z = relu(bn2(y2)) @ W3  ([N,64] x [64,256]) ----------
__global__ __launch_bounds__(128) void k3_gemm(const float* __restrict__ W3)
{
    __shared__ __align__(16) float a_s[64 * 64];
    __shared__ __align__(16) float w_s[64 * 64];
    int tid = threadIdx.x, tx = tid & 7, ty = tid >> 3;
    int bid = blockIdx.x, cb = blockIdx.y;
    int row0 = bid * 64, col0 = cb * 64;

#pragma unroll
    for (int q = 0; q < 8; q++) {
        int fi = tid + q * 128; int r = fi >> 4, c4 = fi & 15; int c0 = c4 * 4;
        float4 v = *(const float4*)&g_y2[(size_t)(row0 + r) * 64 + c0];
        v.x = fmaxf(fmaf(v.x, g_sc2[c0],     g_sh2[c0]),     0.f);
        v.y = fmaxf(fmaf(v.y, g_sc2[c0 + 1], g_sh2[c0 + 1]), 0.f);
        v.z = fmaxf(fmaf(v.z, g_sc2[c0 + 2], g_sh2[c0 + 2]), 0.f);
        v.w = fmaxf(fmaf(v.w, g_sc2[c0 + 3], g_sh2[c0 + 3]), 0.f);
        *(float4*)&a_s[r * 64 + c0] = v;
    }
#pragma unroll
    for (int q = 0; q < 8; q++) {
        int fi = tid + q * 128; int r = fi >> 4, c4 = fi & 15;
        *(float4*)&w_s[r * 64 + c4 * 4] =
            *(const float4*)&W3[(size_t)r * 256 + col0 + c4 * 4];
    }
    __syncthreads();

    ull acc[4][4];
#pragma unroll
    for (int i = 0; i < 4; i++)
#pragma unroll
        for (int j = 0; j < 4; j++) acc[i][j] = 0ull;

#pragma unroll 8
    for (int c = 0; c < 64; c++) {
        ull av0 = pack2(a_s[ ty       * 64 + c]);
        ull av1 = pack2(a_s[(ty + 16) * 64 + c]);
        ull av2 = pack2(a_s[(ty + 32) * 64 + c]);
        ull av3 = pack2(a_s[(ty + 48) * 64 + c]);
#pragma unroll
        for (int j = 0; j < 4; j++) {
            ull wv = *(const ull*)&w_s[c * 64 + 2 * (tx + 8 * j)];
            fma2(acc[0][j], av0, wv);
            fma2(acc[1][j], av1, wv);
            fma2(acc[2][j], av2, wv);
            fma2(acc[3][j], av3, wv);
        }
    }
    epilogue_store_stats(acc, g_z, 256, row0, col0, a_s,
                         g_part3 + (size_t)bid * 512 + col0,
                         g_part3 + (size_t)bid * 512 + 256 + col0,
                         tx, ty, tid);
}

// ---------------- BN stat finalization (single block, deterministic) -------
__device__ __forceinline__ void finalize_body(
    const float* part, int C, const float* gamma, const float* beta,
    float* sc, float* sh)
{
    __shared__ float ssum[1024], ssq[1024];
    int tid = threadIdx.x;
    int c = tid % C, sl = tid / C, nsl = 1024 / C;
    float s = 0.f, q = 0.f;
    for (int b = sl; b < NB; b += nsl) {
        s += part[(size_t)b * 2 * C + c];
        q += part[(size_t)b * 2 * C + C + c];
    }
    ssum[tid] = s; ssq[tid] = q;
    __syncthreads();
    if (tid < C) {
        for (int t = 1; t < nsl; t++) { s += ssum[t * C + c]; q += ssq[t * C + c]; }
        float mean = s / (float)N_NODES;
        float var  = q / (float)N_NODES - mean * mean;
        float r = rsqrtf(var + EPS_BN);
        float scale = gamma[c] * r;
        sc[c] = scale;
        sh[c] = beta[c] - mean * scale;
    }
}
__global__ void f1k(const float* g, const float* b) { finalize_body(g_part1,  64, g, b, g_sc1, g_sh1); }
__global__ void f2k(const float* g, const float* b) { finalize_body(g_part2,  64, g, b, g_sc2, g_sh2); }
__global__ void f3k(const float* g, const float* b) { finalize_body(g_part3, 256, g, b, g_sc3, g_sh3); }

// ---------------- K4: out = relu(bn3(z) + x) -------------------------------
__global__ __launch_bounds__(256) void k4_out(
    const float* __restrict__ x, float* __restrict__ out)
{
    int i = blockIdx.x * 256 + threadIdx.x;       // over N*256/4 float4s
    if (i >= N_NODES * 64) return;
    int c0 = (i & 63) * 4;
    float4 z  = *(const float4*)&g_z[(size_t)i * 4];
    float4 xv = *(const float4*)&x  [(size_t)i * 4];
    float4 o;
    o.x = fmaxf(fmaf(z.x, g_sc3[c0],     g_sh3[c0])     + xv.x, 0.f);
    o.y = fmaxf(fmaf(z.y, g_sc3[c0 + 1], g_sh3[c0 + 1]) + xv.y, 0.f);
    o.z = fmaxf(fmaf(z.z, g_sc3[c0 + 2], g_sh3[c0 + 2]) + xv.z, 0.f);
    o.w = fmaxf(fmaf(z.w, g_sc3[c0 + 3], g_sh3[c0 + 3]) + xv.w, 0.f);
    *(float4*)&out[(size_t)i * 4] = o;
}

// ---------------- launch ---------------------------------------------------
extern "C" void kernel_launch(void* const* d_in, const int* in_sizes, int n_in,
                              void* d_out, int out_size)
{
    const float* x     = (const float*)d_in[0];
    const int*   neigh = (const int*)  d_in[1];
    // d_in[2] = depth (unused)
    const float* W1 = (const float*)d_in[3];
    const float* g1 = (const float*)d_in[4];
    const float* b1 = (const float*)d_in[5];
    const float* W2 = (const float*)d_in[6];
    const float* g2 = (const float*)d_in[7];
    const float* b2 = (const float*)d_in[8];
    const float* W3 = (const float*)d_in[9];
    const float* g3 = (const float*)d_in[10];
    const float* b3 = (const float*)d_in[11];
    float* out = (float*)d_out;

    k1_gemm<<<NB, 128>>>(x, W1);
    f1k<<<1, 1024>>>(g1, b1);
    k2_gather<<<NB, 128>>>(neigh, W2);
    f2k<<<1, 1024>>>(g2, b2);
    k3_gemm<<<dim3(NB, 4), 128>>>(W3);
    f3k<<<1, 1024>>>(g3, b3);
    k4_out<<<(N_NODES * 64 + 255) / 256, 256>>>(x, out);
}

// round 6
// speedup vs baseline: 1.1484x; 1.1484x over previous
#include <cuda_runtime.h>
#include <cstdint>

#define N_NODES 200000
#define NB1 3125            // 64-row tiles for K1/K3
#define NB2 1563            // 128-row tiles for K2
#define EPS_BN 1e-3f

typedef unsigned long long ull;

// ---------------- scratch (device globals; no allocations allowed) ----------
__device__ __align__(16) float    g_y1 [N_NODES * 64];   // x @ W1 (pre-BN)
__device__ __align__(16) uint32_t g_y1t[N_NODES * 64];   // relu(bn1(y1)), tf32, col-permuted
__device__ __align__(16) float    g_y2 [N_NODES * 64];   // conv2 out (pre-BN)
__device__ __align__(16) float    g_z  [N_NODES * 256];  // h2 @ W3 (pre-BN)
__device__ float g_part1[NB1 * 128];
__device__ float g_part2[NB2 * 128];
__device__ float g_part3[NB1 * 512];
__device__ float g_sc1[64],  g_sh1[64];
__device__ float g_sc2[64],  g_sh2[64];
__device__ float g_sc3[256], g_sh3[256];
__device__ __align__(16) uint32_t g_w2t[27 * 4096];      // W2^T, tf32, col-permuted

// ---------------- packed f32x2 helpers (SIMT kernels) -----------------------
__device__ __forceinline__ ull pack2(float x) {
    ull r; asm("mov.b64 %0, {%1, %1};" : "=l"(r) : "f"(x)); return r;
}
__device__ __forceinline__ void fma2(ull& d, ull a, ull b) {
    asm("fma.rn.f32x2 %0, %1, %2, %0;" : "+l"(d) : "l"(a), "l"(b));
}
__device__ __forceinline__ float2 unpk(ull v) {
    float2 r; asm("mov.b64 {%0, %1}, %2;" : "=f"(r.x), "=f"(r.y) : "l"(v)); return r;
}
__device__ __forceinline__ uint32_t to_tf32(float v) {
    uint32_t u; asm("cvt.rna.tf32.f32 %0, %1;" : "=r"(u) : "f"(v)); return u;
}
__device__ __forceinline__ void mma_tf32(float* c,
    uint32_t a0, uint32_t a1, uint32_t a2, uint32_t a3, uint32_t b0, uint32_t b1)
{
    asm volatile(
        "mma.sync.aligned.m16n8k8.row.col.f32.tf32.tf32.f32 "
        "{%0,%1,%2,%3}, {%4,%5,%6,%7}, {%8,%9}, {%0,%1,%2,%3};"
        : "+f"(c[0]), "+f"(c[1]), "+f"(c[2]), "+f"(c[3])
        : "r"(a0), "r"(a1), "r"(a2), "r"(a3), "r"(b0), "r"(b1));
}

// ---------------- shared epilogue for SIMT GEMMs (K1/K3) --------------------
__device__ __forceinline__ void epilogue_store_stats(
    ull acc[4][4], float* ybuf, int ypitch, int row0, int col0,
    float* red, float* psum_out, float* psq_out, int tx, int ty, int tid)
{
    float ps[8], pq[8];
#pragma unroll
    for (int u = 0; u < 8; u++) { ps[u] = 0.f; pq[u] = 0.f; }
#pragma unroll
    for (int i = 0; i < 4; i++) {
        int row = row0 + ty + 16 * i;
#pragma unroll
        for (int j = 0; j < 4; j++) {
            float2 v = unpk(acc[i][j]);
            *(float2*)&ybuf[(size_t)row * ypitch + col0 + 2 * (tx + 8 * j)] = v;
            ps[2 * j]     += v.x;  pq[2 * j]     += v.x * v.x;
            ps[2 * j + 1] += v.y;  pq[2 * j + 1] += v.y * v.y;
        }
    }
    __syncthreads();
#pragma unroll
    for (int j = 0; j < 4; j++) {
        red[ty * 64 + 2 * (tx + 8 * j)]     = ps[2 * j];
        red[ty * 64 + 2 * (tx + 8 * j) + 1] = ps[2 * j + 1];
    }
    __syncthreads();
    if (tid < 64) {
        float s = 0.f;
#pragma unroll
        for (int t = 0; t < 16; t++) s += red[t * 64 + tid];
        psum_out[tid] = s;
    }
    __syncthreads();
#pragma unroll
    for (int j = 0; j < 4; j++) {
        red[ty * 64 + 2 * (tx + 8 * j)]     = pq[2 * j];
        red[ty * 64 + 2 * (tx + 8 * j) + 1] = pq[2 * j + 1];
    }
    __syncthreads();
    if (tid < 64) {
        float s = 0.f;
#pragma unroll
        for (int t = 0; t < 16; t++) s += red[t * 64 + tid];
        psq_out[tid] = s;
    }
}

// ---------------- K1: y1 = x @ W1  (SIMT f32x2) -----------------------------
__global__ __launch_bounds__(128) void k1_gemm(
    const float* __restrict__ x, const float* __restrict__ W1)
{
    __shared__ __align__(16) float x_s[64 * 32];
    __shared__ __align__(16) float w_s[32 * 64];
    int tid = threadIdx.x, tx = tid & 7, ty = tid >> 3;
    int bid = blockIdx.x, row0 = bid * 64;

    ull acc[4][4];
#pragma unroll
    for (int i = 0; i < 4; i++)
#pragma unroll
        for (int j = 0; j < 4; j++) acc[i][j] = 0ull;

    for (int kk = 0; kk < 256; kk += 32) {
#pragma unroll
        for (int q = 0; q < 4; q++) {
            int fi = tid + q * 128; int r = fi >> 3, c4 = fi & 7;
            *(float4*)&x_s[r * 32 + c4 * 4] =
                *(const float4*)&x[(size_t)(row0 + r) * 256 + kk + c4 * 4];
        }
#pragma unroll
        for (int q = 0; q < 4; q++) {
            int fi = tid + q * 128; int r = fi >> 4, c4 = fi & 15;
            *(float4*)&w_s[r * 64 + c4 * 4] =
                *(const float4*)&W1[(size_t)(kk + r) * 64 + c4 * 4];
        }
        __syncthreads();
#pragma unroll
        for (int c = 0; c < 32; c++) {
            ull av0 = pack2(x_s[ ty       * 32 + c]);
            ull av1 = pack2(x_s[(ty + 16) * 32 + c]);
            ull av2 = pack2(x_s[(ty + 32) * 32 + c]);
            ull av3 = pack2(x_s[(ty + 48) * 32 + c]);
#pragma unroll
            for (int j = 0; j < 4; j++) {
                ull wv = *(const ull*)&w_s[c * 64 + 2 * (tx + 8 * j)];
                fma2(acc[0][j], av0, wv);
                fma2(acc[1][j], av1, wv);
                fma2(acc[2][j], av2, wv);
                fma2(acc[3][j], av3, wv);
            }
        }
        __syncthreads();
    }
    epilogue_store_stats(acc, g_y1, 64, row0, 0, x_s,
                         g_part1 + bid * 128, g_part1 + bid * 128 + 64,
                         tx, ty, tid);
}

// ---------------- prep: W2 -> tf32 B^T image, col-permuted ------------------
// g_w2t[k][n][p(c)] = tf32(W2[k][c][n]);  p(c) pairs (c, c+4) adjacently:
// p(c) = (c>>3)*8 + (c&3)*2 + ((c&7)>>2)
__global__ void prep_w2(const float* __restrict__ W2) {
    int k = blockIdx.x;
    for (int e = threadIdx.x; e < 4096; e += blockDim.x) {
        int c = e >> 6, n = e & 63;
        uint32_t u = to_tf32(W2[(size_t)k * 4096 + e]);
        int p = ((c >> 3) << 3) + ((c & 3) << 1) + ((c & 7) >> 2);
        g_w2t[(size_t)k * 4096 + n * 64 + p] = u;
    }
}

// ---------------- k1b: g_y1t = permute(tf32(relu(bn1(y1)))) -----------------
__global__ __launch_bounds__(256) void k1b()
{
    size_t i = (size_t)blockIdx.x * 256 + threadIdx.x;   // float4 index
    if (i >= (size_t)N_NODES * 16) return;
    int c4 = (int)(i & 15), cb = c4 * 4;
    float4 v = *(const float4*)&g_y1[i * 4];
    uint32_t u0 = to_tf32(fmaxf(fmaf(v.x, g_sc1[cb],     g_sh1[cb]),     0.f));
    uint32_t u1 = to_tf32(fmaxf(fmaf(v.y, g_sc1[cb + 1], g_sh1[cb + 1]), 0.f));
    uint32_t u2 = to_tf32(fmaxf(fmaf(v.z, g_sc1[cb + 2], g_sh1[cb + 2]), 0.f));
    uint32_t u3 = to_tf32(fmaxf(fmaf(v.w, g_sc1[cb + 3], g_sh1[cb + 3]), 0.f));
    // cols cb..cb+3 -> positions grp*8 + odd + {0,2,4,6}
    int grp = c4 >> 1, odd = c4 & 1;
    uint32_t* dst = g_y1t + (i >> 4) * 64 + grp * 8 + odd;
    dst[0] = u0; dst[2] = u1; dst[4] = u2; dst[6] = u3;
}

// ---------------- K2: tf32 mma.sync gather-GEMM -----------------------------
// CTA: 256 thr / 8 warps, 128 rows x 64 cols. Per neighbor k: gather A
// (128x64 tf32, pre-activated), copy B tile, 64 mma per warp.
#define K2_AS   0        // u32 offsets into dynamic smem
#define K2_BS   8704     // 128*68
#define K2_IDX  13056    // + 64*68
#define K2_PS   16512    // + 128*27
#define K2_PQ   17024
#define K2_U32  17536    // 70144 bytes

__global__ __launch_bounds__(256, 1) void k2_tc(const int* __restrict__ neigh)
{
    extern __shared__ uint32_t dsm[];
    uint32_t* As   = dsm + K2_AS;     // [128][68]
    uint32_t* Bs   = dsm + K2_BS;     // [64][68]
    int*      sidx = (int*)(dsm + K2_IDX);
    float*    psum = (float*)(dsm + K2_PS);
    float*    psq  = (float*)(dsm + K2_PQ);

    int tid = threadIdx.x, wid = tid >> 5, lane = tid & 31;
    int g = lane >> 2, t = lane & 3;
    int bid = blockIdx.x, row0 = bid * 128;
    int nval = N_NODES - row0; if (nval > 128) nval = 128;

    // preload neighbor indices
    for (int i = tid; i < nval * 27; i += 256)
        sidx[i] = neigh[(size_t)row0 * 27 + i];

    float acc[8][4];
#pragma unroll
    for (int nt = 0; nt < 8; nt++)
#pragma unroll
        for (int j = 0; j < 4; j++) acc[nt][j] = 0.f;

    int grow = tid >> 1;               // gather row 0..127
    int h8   = (tid & 1) * 8;          // uint4 half-row
    bool gvalid = grow < nval;

    for (int k = 0; k < 27; k++) {
        __syncthreads();               // previous compute done reading As/Bs
        // B tile copy (pre-permuted image), row stride 68
        {
            const uint4* src = (const uint4*)(g_w2t + (size_t)k * 4096);
            uint4* dstv = (uint4*)Bs;
#pragma unroll
            for (int q = 0; q < 4; q++) {
                int e = tid + q * 256;         // 0..1023
                int n = e >> 4, w = e & 15;
                dstv[n * 17 + w] = src[e];
            }
        }
        // A gather: one row per thread-pair, 8 uint4 each
        {
            uint4 z; z.x = 0u; z.y = 0u; z.z = 0u; z.w = 0u;
            const uint4* src = nullptr;
            if (gvalid) {
                int gi = sidx[grow * 27 + k];
                src = (const uint4*)(g_y1t + (size_t)gi * 64);
            }
            uint4* dstv = (uint4*)(As + grow * 68);
#pragma unroll
            for (int q = 0; q < 8; q++)
                dstv[h8 + q] = gvalid ? src[h8 + q] : z;
        }
        __syncthreads();
        // compute: each warp owns 16 rows
        int rA = wid * 16 + g;
#pragma unroll
        for (int kk = 0; kk < 8; kk++) {
            int co = kk * 8 + t * 2;
            uint2 aLo = *(const uint2*)&As[ rA      * 68 + co];
            uint2 aHi = *(const uint2*)&As[(rA + 8) * 68 + co];
#pragma unroll
            for (int nt = 0; nt < 8; nt++) {
                uint2 b = *(const uint2*)&Bs[(nt * 8 + g) * 68 + co];
                mma_tf32(acc[nt], aLo.x, aHi.x, aLo.y, aHi.y, b.x, b.y);
            }
        }
    }

    // epilogue: store y2 + BN2 stat partials
    int rowA = row0 + wid * 16 + g, rowB = rowA + 8;
#pragma unroll
    for (int nt = 0; nt < 8; nt++) {
        float c0 = acc[nt][0], c1 = acc[nt][1], c2 = acc[nt][2], c3 = acc[nt][3];
        if (rowA < N_NODES) {
            float2 v; v.x = c0; v.y = c1;
            *(float2*)&g_y2[(size_t)rowA * 64 + nt * 8 + t * 2] = v;
        }
        if (rowB < N_NODES) {
            float2 v; v.x = c2; v.y = c3;
            *(float2*)&g_y2[(size_t)rowB * 64 + nt * 8 + t * 2] = v;
        }
        float s0 = c0 + c2, s1 = c1 + c3;
        float q0 = c0 * c0 + c2 * c2, q1 = c1 * c1 + c3 * c3;
#pragma unroll
        for (int d = 4; d <= 16; d <<= 1) {
            s0 += __shfl_xor_sync(0xFFFFFFFFu, s0, d);
            s1 += __shfl_xor_sync(0xFFFFFFFFu, s1, d);
            q0 += __shfl_xor_sync(0xFFFFFFFFu, q0, d);
            q1 += __shfl_xor_sync(0xFFFFFFFFu, q1, d);
        }
        if (g == 0) {
            psum[wid * 64 + nt * 8 + t * 2]     = s0;
            psum[wid * 64 + nt * 8 + t * 2 + 1] = s1;
            psq [wid * 64 + nt * 8 + t * 2]     = q0;
            psq [wid * 64 + nt * 8 + t * 2 + 1] = q1;
        }
    }
    __syncthreads();
    if (tid < 64) {
        float s = 0.f, q = 0.f;
#pragma unroll
        for (int w = 0; w < 8; w++) { s += psum[w * 64 + tid]; q += psq[w * 64 + tid]; }
        g_part2[bid * 128 + tid]      = s;
        g_part2[bid * 128 + 64 + tid] = q;
    }
}

// ---------------- K3: z = relu(bn2(y2)) @ W3 (SIMT f32x2) -------------------
__global__ __launch_bounds__(128) void k3_gemm(const float* __restrict__ W3)
{
    __shared__ __align__(16) float a_s[64 * 64];
    __shared__ __align__(16) float w_s[64 * 64];
    int tid = threadIdx.x, tx = tid & 7, ty = tid >> 3;
    int bid = blockIdx.x, cb = blockIdx.y;
    int row0 = bid * 64, col0 = cb * 64;

#pragma unroll
    for (int q = 0; q < 8; q++) {
        int fi = tid + q * 128; int r = fi >> 4, c4 = fi & 15; int c0 = c4 * 4;
        float4 v = *(const float4*)&g_y2[(size_t)(row0 + r) * 64 + c0];
        v.x = fmaxf(fmaf(v.x, g_sc2[c0],     g_sh2[c0]),     0.f);
        v.y = fmaxf(fmaf(v.y, g_sc2[c0 + 1], g_sh2[c0 + 1]), 0.f);
        v.z = fmaxf(fmaf(v.z, g_sc2[c0 + 2], g_sh2[c0 + 2]), 0.f);
        v.w = fmaxf(fmaf(v.w, g_sc2[c0 + 3], g_sh2[c0 + 3]), 0.f);
        *(float4*)&a_s[r * 64 + c0] = v;
    }
#pragma unroll
    for (int q = 0; q < 8; q++) {
        int fi = tid + q * 128; int r = fi >> 4, c4 = fi & 15;
        *(float4*)&w_s[r * 64 + c4 * 4] =
            *(const float4*)&W3[(size_t)r * 256 + col0 + c4 * 4];
    }
    __syncthreads();

    ull acc[4][4];
#pragma unroll
    for (int i = 0; i < 4; i++)
#pragma unroll
        for (int j = 0; j < 4; j++) acc[i][j] = 0ull;

#pragma unroll 8
    for (int c = 0; c < 64; c++) {
        ull av0 = pack2(a_s[ ty       * 64 + c]);
        ull av1 = pack2(a_s[(ty + 16) * 64 + c]);
        ull av2 = pack2(a_s[(ty + 32) * 64 + c]);
        ull av3 = pack2(a_s[(ty + 48) * 64 + c]);
#pragma unroll
        for (int j = 0; j < 4; j++) {
            ull wv = *(const ull*)&w_s[c * 64 + 2 * (tx + 8 * j)];
            fma2(acc[0][j], av0, wv);
            fma2(acc[1][j], av1, wv);
            fma2(acc[2][j], av2, wv);
            fma2(acc[3][j], av3, wv);
        }
    }
    epilogue_store_stats(acc, g_z, 256, row0, col0, a_s,
                         g_part3 + (size_t)bid * 512 + col0,
                         g_part3 + (size_t)bid * 512 + 256 + col0,
                         tx, ty, tid);
}

// ---------------- BN finalize: one block per channel ------------------------
__device__ __forceinline__ void fin_body(
    const float* part, int nb, int C, const float* gamma, const float* beta,
    float* sc, float* sh)
{
    __shared__ float ss[256], sq[256];
    int c = blockIdx.x, t = threadIdx.x;
    float s = 0.f, q = 0.f;
    for (int b = t; b < nb; b += 256) {
        s += part[(size_t)b * 2 * C + c];
        q += part[(size_t)b * 2 * C + C + c];
    }
    ss[t] = s; sq[t] = q; __syncthreads();
    for (int d = 128; d; d >>= 1) {
        if (t < d) { ss[t] += ss[t + d]; sq[t] += sq[t + d]; }
        __syncthreads();
    }
    if (t == 0) {
        float mean = ss[0] / (float)N_NODES;
        float var  = sq[0] / (float)N_NODES - mean * mean;
        float r = rsqrtf(var + EPS_BN);
        float scale = gamma[c] * r;
        sc[c] = scale;
        sh[c] = beta[c] - mean * scale;
    }
}
__global__ void f1k(const float* g, const float* b) { fin_body(g_part1, NB1,  64, g, b, g_sc1, g_sh1); }
__global__ void f2k(const float* g, const float* b) { fin_body(g_part2, NB2,  64, g, b, g_sc2, g_sh2); }
__global__ void f3k(const float* g, const float* b) { fin_body(g_part3, NB1, 256, g, b, g_sc3, g_sh3); }

// ---------------- K4: out = relu(bn3(z) + x) --------------------------------
__global__ __launch_bounds__(256) void k4_out(
    const float* __restrict__ x, float* __restrict__ out)
{
    int i = blockIdx.x * 256 + threadIdx.x;
    if (i >= N_NODES * 64) return;
    int c0 = (i & 63) * 4;
    float4 z  = *(const float4*)&g_z[(size_t)i * 4];
    float4 xv = *(const float4*)&x  [(size_t)i * 4];
    float4 o;
    o.x = fmaxf(fmaf(z.x, g_sc3[c0],     g_sh3[c0])     + xv.x, 0.f);
    o.y = fmaxf(fmaf(z.y, g_sc3[c0 + 1], g_sh3[c0 + 1]) + xv.y, 0.f);
    o.z = fmaxf(fmaf(z.z, g_sc3[c0 + 2], g_sh3[c0 + 2]) + xv.z, 0.f);
    o.w = fmaxf(fmaf(z.w, g_sc3[c0 + 3], g_sh3[c0 + 3]) + xv.w, 0.f);
    *(float4*)&out[(size_t)i * 4] = o;
}

// ---------------- launch ---------------------------------------------------
extern "C" void kernel_launch(void* const* d_in, const int* in_sizes, int n_in,
                              void* d_out, int out_size)
{
    const float* x     = (const float*)d_in[0];
    const int*   neigh = (const int*)  d_in[1];
    const float* W1 = (const float*)d_in[3];
    const float* g1 = (const float*)d_in[4];
    const float* b1 = (const float*)d_in[5];
    const float* W2 = (const float*)d_in[6];
    const float* g2 = (const float*)d_in[7];
    const float* b2 = (const float*)d_in[8];
    const float* W3 = (const float*)d_in[9];
    const float* g3 = (const float*)d_in[10];
    const float* b3 = (const float*)d_in[11];
    float* out = (float*)d_out;

    cudaFuncSetAttribute(k2_tc, cudaFuncAttributeMaxDynamicSharedMemorySize,
                         K2_U32 * 4);

    prep_w2<<<27, 256>>>(W2);
    k1_gemm<<<NB1, 128>>>(x, W1);
    f1k<<<64, 256>>>(g1, b1);
    k1b<<<(N_NODES * 16 + 255) / 256, 256>>>();
    k2_tc<<<NB2, 256, K2_U32 * 4>>>(neigh);
    f2k<<<64, 256>>>(g2, b2);
    k3_gemm<<<dim3(NB1, 4), 128>>>(W3);
    f3k<<<256, 256>>>(g3, b3);
    k4_out<<<(N_NODES * 64 + 255) / 256, 256>>>(x, out);
}

// round 7
// speedup vs baseline: 1.3832x; 1.2045x over previous
#include <cuda_runtime.h>
#include <cstdint>

#define N_NODES 200000
#define NB1 3125            // 64-row tiles for K1/K3
#define NB2 1563            // 128-row tiles for K2
#define EPS_BN 1e-3f

typedef unsigned long long ull;

// ---------------- scratch (device globals; no allocations allowed) ----------
__device__ __align__(16) float    g_y1 [N_NODES * 64];   // x @ W1 (pre-BN)
__device__ __align__(16) uint32_t g_y1t[N_NODES * 64];   // relu(bn1(y1)), tf32, col-permuted
__device__ __align__(16) float    g_y2 [N_NODES * 64];   // conv2 out (pre-BN)
__device__ __align__(16) float    g_z  [N_NODES * 256];  // h2 @ W3 (pre-BN)
__device__ float g_part1[NB1 * 128];
__device__ float g_part2[NB2 * 128];
__device__ float g_part3[NB1 * 512];
__device__ float g_sc1[64],  g_sh1[64];
__device__ float g_sc2[64],  g_sh2[64];
__device__ float g_sc3[256], g_sh3[256];
__device__ __align__(16) uint32_t g_w2t[27 * 4096];      // W2^T, tf32, col-permuted

// ---------------- helpers ---------------------------------------------------
__device__ __forceinline__ ull pack2(float x) {
    ull r; asm("mov.b64 %0, {%1, %1};" : "=l"(r) : "f"(x)); return r;
}
__device__ __forceinline__ void fma2(ull& d, ull a, ull b) {
    asm("fma.rn.f32x2 %0, %1, %2, %0;" : "+l"(d) : "l"(a), "l"(b));
}
__device__ __forceinline__ float2 unpk(ull v) {
    float2 r; asm("mov.b64 {%0, %1}, %2;" : "=f"(r.x), "=f"(r.y) : "l"(v)); return r;
}
__device__ __forceinline__ uint32_t to_tf32(float v) {
    uint32_t u; asm("cvt.rna.tf32.f32 %0, %1;" : "=r"(u) : "f"(v)); return u;
}
__device__ __forceinline__ uint32_t smem_u32(const void* p) {
    uint32_t a; asm("{ .reg .u64 t; cvta.to.shared.u64 t, %1; cvt.u32.u64 %0, t; }"
                    : "=r"(a) : "l"(p));
    return a;
}
__device__ __forceinline__ void mma_tf32(float* c,
    uint32_t a0, uint32_t a1, uint32_t a2, uint32_t a3, uint32_t b0, uint32_t b1)
{
    asm volatile(
        "mma.sync.aligned.m16n8k8.row.col.f32.tf32.tf32.f32 "
        "{%0,%1,%2,%3}, {%4,%5,%6,%7}, {%8,%9}, {%0,%1,%2,%3};"
        : "+f"(c[0]), "+f"(c[1]), "+f"(c[2]), "+f"(c[3])
        : "r"(a0), "r"(a1), "r"(a2), "r"(a3), "r"(b0), "r"(b1));
}
__device__ __forceinline__ void cp16(uint32_t dst, const void* src) {
    asm volatile("cp.async.cg.shared.global [%0], [%1], 16;" :: "r"(dst), "l"(src));
}
__device__ __forceinline__ void cp16p(uint32_t dst, const void* src, int ssz) {
    asm volatile("cp.async.cg.shared.global [%0], [%1], 16, %2;"
                 :: "r"(dst), "l"(src), "r"(ssz));
}

// ---------------- shared epilogue for SIMT GEMMs (K1/K3) --------------------
__device__ __forceinline__ void epilogue_store_stats(
    ull acc[4][4], float* ybuf, int ypitch, int row0, int col0,
    float* red, float* psum_out, float* psq_out, int tx, int ty, int tid)
{
    float ps[8], pq[8];
#pragma unroll
    for (int u = 0; u < 8; u++) { ps[u] = 0.f; pq[u] = 0.f; }
#pragma unroll
    for (int i = 0; i < 4; i++) {
        int row = row0 + ty + 16 * i;
#pragma unroll
        for (int j = 0; j < 4; j++) {
            float2 v = unpk(acc[i][j]);
            *(float2*)&ybuf[(size_t)row * ypitch + col0 + 2 * (tx + 8 * j)] = v;
            ps[2 * j]     += v.x;  pq[2 * j]     += v.x * v.x;
            ps[2 * j + 1] += v.y;  pq[2 * j + 1] += v.y * v.y;
        }
    }
    __syncthreads();
#pragma unroll
    for (int j = 0; j < 4; j++) {
        red[ty * 64 + 2 * (tx + 8 * j)]     = ps[2 * j];
        red[ty * 64 + 2 * (tx + 8 * j) + 1] = ps[2 * j + 1];
    }
    __syncthreads();
    if (tid < 64) {
        float s = 0.f;
#pragma unroll
        for (int t = 0; t < 16; t++) s += red[t * 64 + tid];
        psum_out[tid] = s;
    }
    __syncthreads();
#pragma unroll
    for (int j = 0; j < 4; j++) {
        red[ty * 64 + 2 * (tx + 8 * j)]     = pq[2 * j];
        red[ty * 64 + 2 * (tx + 8 * j) + 1] = pq[2 * j + 1];
    }
    __syncthreads();
    if (tid < 64) {
        float s = 0.f;
#pragma unroll
        for (int t = 0; t < 16; t++) s += red[t * 64 + tid];
        psq_out[tid] = s;
    }
}

// ---------------- K1: y1 = x @ W1  (SIMT f32x2) -----------------------------
__global__ __launch_bounds__(128) void k1_gemm(
    const float* __restrict__ x, const float* __restrict__ W1)
{
    __shared__ __align__(16) float x_s[64 * 32];
    __shared__ __align__(16) float w_s[32 * 64];
    int tid = threadIdx.x, tx = tid & 7, ty = tid >> 3;
    int bid = blockIdx.x, row0 = bid * 64;

    ull acc[4][4];
#pragma unroll
    for (int i = 0; i < 4; i++)
#pragma unroll
        for (int j = 0; j < 4; j++) acc[i][j] = 0ull;

    for (int kk = 0; kk < 256; kk += 32) {
#pragma unroll
        for (int q = 0; q < 4; q++) {
            int fi = tid + q * 128; int r = fi >> 3, c4 = fi & 7;
            *(float4*)&x_s[r * 32 + c4 * 4] =
                *(const float4*)&x[(size_t)(row0 + r) * 256 + kk + c4 * 4];
        }
#pragma unroll
        for (int q = 0; q < 4; q++) {
            int fi = tid + q * 128; int r = fi >> 4, c4 = fi & 15;
            *(float4*)&w_s[r * 64 + c4 * 4] =
                *(const float4*)&W1[(size_t)(kk + r) * 64 + c4 * 4];
        }
        __syncthreads();
#pragma unroll
        for (int c = 0; c < 32; c++) {
            ull av0 = pack2(x_s[ ty       * 32 + c]);
            ull av1 = pack2(x_s[(ty + 16) * 32 + c]);
            ull av2 = pack2(x_s[(ty + 32) * 32 + c]);
            ull av3 = pack2(x_s[(ty + 48) * 32 + c]);
#pragma unroll
            for (int j = 0; j < 4; j++) {
                ull wv = *(const ull*)&w_s[c * 64 + 2 * (tx + 8 * j)];
                fma2(acc[0][j], av0, wv);
                fma2(acc[1][j], av1, wv);
                fma2(acc[2][j], av2, wv);
                fma2(acc[3][j], av3, wv);
            }
        }
        __syncthreads();
    }
    epilogue_store_stats(acc, g_y1, 64, row0, 0, x_s,
                         g_part1 + bid * 128, g_part1 + bid * 128 + 64,
                         tx, ty, tid);
}

// ---------------- BN finalize body ------------------------------------------
__device__ __forceinline__ void fin_body(
    const float* part, int nb, int C, const float* gamma, const float* beta,
    float* sc, float* sh)
{
    __shared__ float ss[256], sq[256];
    int c = blockIdx.x, t = threadIdx.x;
    float s = 0.f, q = 0.f;
    for (int b = t; b < nb; b += 256) {
        s += part[(size_t)b * 2 * C + c];
        q += part[(size_t)b * 2 * C + C + c];
    }
    ss[t] = s; sq[t] = q; __syncthreads();
    for (int d = 128; d; d >>= 1) {
        if (t < d) { ss[t] += ss[t + d]; sq[t] += sq[t + d]; }
        __syncthreads();
    }
    if (t == 0) {
        float mean = ss[0] / (float)N_NODES;
        float var  = sq[0] / (float)N_NODES - mean * mean;
        float r = rsqrtf(var + EPS_BN);
        float scale = gamma[c] * r;
        sc[c] = scale;
        sh[c] = beta[c] - mean * scale;
    }
}

// ---------------- f1p: BN1 finalize + W2 prep (fused to keep k2 at slot 4) --
// g_w2t[k][n][p(c)] = tf32(W2[k][c][n]);  p(c) = (c>>3)*8 + (c&3)*2 + ((c>>2)&1)
__global__ void f1p(const float* g, const float* b, const float* __restrict__ W2)
{
    fin_body(g_part1, NB1, 64, g, b, g_sc1, g_sh1);
    for (int i = blockIdx.x * 256 + threadIdx.x; i < 27 * 4096; i += 64 * 256) {
        int k = i >> 12, e = i & 4095;
        int c = e >> 6, n = e & 63;
        uint32_t u = to_tf32(W2[i]);
        int p = ((c >> 3) << 3) + ((c & 3) << 1) + ((c & 7) >> 2);
        g_w2t[(size_t)k * 4096 + n * 64 + p] = u;
    }
}

// ---------------- k1b: g_y1t = permute(tf32(relu(bn1(y1)))) -----------------
__global__ __launch_bounds__(256) void k1b()
{
    size_t i = (size_t)blockIdx.x * 256 + threadIdx.x;   // float4 index
    if (i >= (size_t)N_NODES * 16) return;
    int c4 = (int)(i & 15), cb = c4 * 4;
    float4 v = *(const float4*)&g_y1[i * 4];
    uint32_t u0 = to_tf32(fmaxf(fmaf(v.x, g_sc1[cb],     g_sh1[cb]),     0.f));
    uint32_t u1 = to_tf32(fmaxf(fmaf(v.y, g_sc1[cb + 1], g_sh1[cb + 1]), 0.f));
    uint32_t u2 = to_tf32(fmaxf(fmaf(v.z, g_sc1[cb + 2], g_sh1[cb + 2]), 0.f));
    uint32_t u3 = to_tf32(fmaxf(fmaf(v.w, g_sc1[cb + 3], g_sh1[cb + 3]), 0.f));
    int grp = c4 >> 1, odd = c4 & 1;
    uint32_t* dst = g_y1t + (i >> 4) * 64 + grp * 8 + odd;
    dst[0] = u0; dst[2] = u1; dst[4] = u2; dst[6] = u3;
}

// ---------------- K2: tf32 mma.sync gather-GEMM, cp.async double-buffered ---
// 256 thr / 8 warps; 128 rows x 64 cols per CTA.
// Warp grid 4x2: warp w -> rows (w>>1)*32..+32, cols (w&1)*32..+32.
#define K2_AS   0        // word offsets: A 2 x 128 x 68
#define K2_BS   17408    // B 2 x 64 x 68
#define K2_IDX  26112    // 128*27 idx
#define K2_PS   29568    // 4 x 64
#define K2_PQ   29824    // 4 x 64
#define K2_U32  30080    // 120320 bytes

__device__ __forceinline__ void k2_issue(
    uint32_t sbase, int tid, int grow, int h, int gvalid, const int* sidx,
    int k, int buf)
{
    // B tile: 64 rows x 16 uint4, 4 per thread
    const char* bs = (const char*)(g_w2t + (size_t)k * 4096);
#pragma unroll
    for (int q = 0; q < 4; q++) {
        int e = tid + q * 256, n = e >> 4, w = e & 15;
        cp16(sbase + (K2_BS + buf * 4352 + n * 68 + w * 4) * 4,
             bs + (n * 64 + w * 4) * 4);
    }
    // A gather: half-row (8 uint4) per thread
    int gi = gvalid ? sidx[grow * 27 + k] : 0;
    const char* as = (const char*)(g_y1t + (size_t)gi * 64 + h * 4);
    uint32_t dst = sbase + (K2_AS + buf * 8704 + grow * 68 + h * 4) * 4;
    int ssz = gvalid ? 16 : 0;
#pragma unroll
    for (int q = 0; q < 8; q++)
        cp16p(dst + q * 16, as + q * 16, ssz);
    asm volatile("cp.async.commit_group;" ::: "memory");
}

__global__ __launch_bounds__(256, 1) void k2_tc(const int* __restrict__ neigh)
{
    extern __shared__ uint32_t dsm[];
    uint32_t sbase = smem_u32(dsm);
    int*   sidx = (int*)(dsm + K2_IDX);
    float* psum = (float*)(dsm + K2_PS);
    float* psq  = (float*)(dsm + K2_PQ);

    int tid = threadIdx.x, wid = tid >> 5, lane = tid & 31;
    int g = lane >> 2, t = lane & 3;
    int rg = wid >> 1, cg = wid & 1;
    int bid = blockIdx.x, row0 = bid * 128;
    int nval = N_NODES - row0; if (nval > 128) nval = 128;

    for (int i = tid; i < nval * 27; i += 256)
        sidx[i] = neigh[(size_t)row0 * 27 + i];
    __syncthreads();

    int grow = tid >> 1;
    int h    = (tid & 1) * 8;
    int gvalid = grow < nval;

    float acc[2][4][4];
#pragma unroll
    for (int i = 0; i < 2; i++)
#pragma unroll
        for (int j = 0; j < 4; j++)
#pragma unroll
            for (int u = 0; u < 4; u++) acc[i][j][u] = 0.f;

    k2_issue(sbase, tid, grow, h, gvalid, sidx, 0, 0);

    int ra0 = rg * 32 + g;
    for (int k = 0; k < 27; k++) {
        int buf = k & 1;
        asm volatile("cp.async.wait_group 0;" ::: "memory");
        __syncthreads();
        if (k + 1 < 27)
            k2_issue(sbase, tid, grow, h, gvalid, sidx, k + 1, buf ^ 1);
        const uint32_t* As = dsm + K2_AS + buf * 8704;
        const uint32_t* Bs = dsm + K2_BS + buf * 4352;
#pragma unroll
        for (int kk = 0; kk < 8; kk++) {
            int co = kk * 8 + t * 2;
            uint2 a00 = *(const uint2*)&As[(ra0     ) * 68 + co];
            uint2 a01 = *(const uint2*)&As[(ra0 +  8) * 68 + co];
            uint2 a10 = *(const uint2*)&As[(ra0 + 16) * 68 + co];
            uint2 a11 = *(const uint2*)&As[(ra0 + 24) * 68 + co];
#pragma unroll
            for (int j = 0; j < 4; j++) {
                int nt = cg * 4 + j;
                uint2 b = *(const uint2*)&Bs[(nt * 8 + g) * 68 + co];
                mma_tf32(acc[0][j], a00.x, a01.x, a00.y, a01.y, b.x, b.y);
                mma_tf32(acc[1][j], a10.x, a11.x, a10.y, a11.y, b.x, b.y);
            }
        }
    }

    // epilogue: store y2 + BN2 stat partials
    int rbase = row0 + rg * 32 + g;
#pragma unroll
    for (int j = 0; j < 4; j++) {
        int col = cg * 32 + j * 8 + t * 2;
        float s0 = 0.f, s1 = 0.f, q0 = 0.f, q1 = 0.f;
#pragma unroll
        for (int i = 0; i < 2; i++) {
            float c0 = acc[i][j][0], c1 = acc[i][j][1];
            float c2 = acc[i][j][2], c3 = acc[i][j][3];
            int rowA = rbase + i * 16, rowB = rowA + 8;
            if (rowA < N_NODES) {
                float2 v; v.x = c0; v.y = c1;
                *(float2*)&g_y2[(size_t)rowA * 64 + col] = v;
            }
            if (rowB < N_NODES) {
                float2 v; v.x = c2; v.y = c3;
                *(float2*)&g_y2[(size_t)rowB * 64 + col] = v;
            }
            s0 += c0 + c2;  s1 += c1 + c3;
            q0 += c0 * c0 + c2 * c2;  q1 += c1 * c1 + c3 * c3;
        }
#pragma unroll
        for (int d = 4; d <= 16; d <<= 1) {
            s0 += __shfl_xor_sync(0xFFFFFFFFu, s0, d);
            s1 += __shfl_xor_sync(0xFFFFFFFFu, s1, d);
            q0 += __shfl_xor_sync(0xFFFFFFFFu, q0, d);
            q1 += __shfl_xor_sync(0xFFFFFFFFu, q1, d);
        }
        if (g == 0) {
            psum[rg * 64 + col]     = s0;
            psum[rg * 64 + col + 1] = s1;
            psq [rg * 64 + col]     = q0;
            psq [rg * 64 + col + 1] = q1;
        }
    }
    __syncthreads();
    if (tid < 64) {
        float s = 0.f, q = 0.f;
#pragma unroll
        for (int w = 0; w < 4; w++) { s += psum[w * 64 + tid]; q += psq[w * 64 + tid]; }
        g_part2[bid * 128 + tid]      = s;
        g_part2[bid * 128 + 64 + tid] = q;
    }
}

// ---------------- K3: z = relu(bn2(y2)) @ W3 (SIMT f32x2) -------------------
__global__ __launch_bounds__(128) void k3_gemm(const float* __restrict__ W3)
{
    __shared__ __align__(16) float a_s[64 * 64];
    __shared__ __align__(16) float w_s[64 * 64];
    int tid = threadIdx.x, tx = tid & 7, ty = tid >> 3;
    int bid = blockIdx.x, cb = blockIdx.y;
    int row0 = bid * 64, col0 = cb * 64;

#pragma unroll
    for (int q = 0; q < 8; q++) {
        int fi = tid + q * 128; int r = fi >> 4, c4 = fi & 15; int c0 = c4 * 4;
        float4 v = *(const float4*)&g_y2[(size_t)(row0 + r) * 64 + c0];
        v.x = fmaxf(fmaf(v.x, g_sc2[c0],     g_sh2[c0]),     0.f);
        v.y = fmaxf(fmaf(v.y, g_sc2[c0 + 1], g_sh2[c0 + 1]), 0.f);
        v.z = fmaxf(fmaf(v.z, g_sc2[c0 + 2], g_sh2[c0 + 2]), 0.f);
        v.w = fmaxf(fmaf(v.w, g_sc2[c0 + 3], g_sh2[c0 + 3]), 0.f);
        *(float4*)&a_s[r * 64 + c0] = v;
    }
#pragma unroll
    for (int q = 0; q < 8; q++) {
        int fi = tid + q * 128; int r = fi >> 4, c4 = fi & 15;
        *(float4*)&w_s[r * 64 + c4 * 4] =
            *(const float4*)&W3[(size_t)r * 256 + col0 + c4 * 4];
    }
    __syncthreads();

    ull acc[4][4];
#pragma unroll
    for (int i = 0; i < 4; i++)
#pragma unroll
        for (int j = 0; j < 4; j++) acc[i][j] = 0ull;

#pragma unroll 8
    for (int c = 0; c < 64; c++) {
        ull av0 = pack2(a_s[ ty       * 64 + c]);
        ull av1 = pack2(a_s[(ty + 16) * 64 + c]);
        ull av2 = pack2(a_s[(ty + 32) * 64 + c]);
        ull av3 = pack2(a_s[(ty + 48) * 64 + c]);
#pragma unroll
        for (int j = 0; j < 4; j++) {
            ull wv = *(const ull*)&w_s[c * 64 + 2 * (tx + 8 * j)];
            fma2(acc[0][j], av0, wv);
            fma2(acc[1][j], av1, wv);
            fma2(acc[2][j], av2, wv);
            fma2(acc[3][j], av3, wv);
        }
    }
    epilogue_store_stats(acc, g_z, 256, row0, col0, a_s,
                         g_part3 + (size_t)bid * 512 + col0,
                         g_part3 + (size_t)bid * 512 + 256 + col0,
                         tx, ty, tid);
}

__global__ void f2k(const float* g, const float* b) { fin_body(g_part2, NB2,  64, g, b, g_sc2, g_sh2); }
__global__ void f3k(const float* g, const float* b) { fin_body(g_part3, NB1, 256, g, b, g_sc3, g_sh3); }

// ---------------- K4: out = relu(bn3(z) + x) --------------------------------
__global__ __launch_bounds__(256) void k4_out(
    const float* __restrict__ x, float* __restrict__ out)
{
    int i = blockIdx.x * 256 + threadIdx.x;
    if (i >= N_NODES * 64) return;
    int c0 = (i & 63) * 4;
    float4 z  = *(const float4*)&g_z[(size_t)i * 4];
    float4 xv = *(const float4*)&x  [(size_t)i * 4];
    float4 o;
    o.x = fmaxf(fmaf(z.x, g_sc3[c0],     g_sh3[c0])     + xv.x, 0.f);
    o.y = fmaxf(fmaf(z.y, g_sc3[c0 + 1], g_sh3[c0 + 1]) + xv.y, 0.f);
    o.z = fmaxf(fmaf(z.z, g_sc3[c0 + 2], g_sh3[c0 + 2]) + xv.z, 0.f);
    o.w = fmaxf(fmaf(z.w, g_sc3[c0 + 3], g_sh3[c0 + 3]) + xv.w, 0.f);
    *(float4*)&out[(size_t)i * 4] = o;
}

// ---------------- launch ---------------------------------------------------
extern "C" void kernel_launch(void* const* d_in, const int* in_sizes, int n_in,
                              void* d_out, int out_size)
{
    const float* x     = (const float*)d_in[0];
    const int*   neigh = (const int*)  d_in[1];
    const float* W1 = (const float*)d_in[3];
    const float* g1 = (const float*)d_in[4];
    const float* b1 = (const float*)d_in[5];
    const float* W2 = (const float*)d_in[6];
    const float* g2 = (const float*)d_in[7];
    const float* b2 = (const float*)d_in[8];
    const float* W3 = (const float*)d_in[9];
    const float* g3 = (const float*)d_in[10];
    const float* b3 = (const float*)d_in[11];
    float* out = (float*)d_out;

    cudaFuncSetAttribute(k2_tc, cudaFuncAttributeMaxDynamicSharedMemorySize,
                         K2_U32 * 4);

    k1_gemm<<<NB1, 128>>>(x, W1);                       // launch 1
    f1p<<<64, 256>>>(g1, b1, W2);                       // launch 2 (BN1 + W2 prep)
    k1b<<<(N_NODES * 16 + 255) / 256, 256>>>();         // launch 3
    k2_tc<<<NB2, 256, K2_U32 * 4>>>(neigh);             // launch 4 (profiled slot)
    f2k<<<64, 256>>>(g2, b2);                           // launch 5
    k3_gemm<<<dim3(NB1, 4), 128>>>(W3);                 // launch 6
    f3k<<<256, 256>>>(g3, b3);                          // launch 7
    k4_out<<<(N_NODES * 64 + 255) / 256, 256>>>(x, out);// launch 8
}

// round 10
// speedup vs baseline: 1.4743x; 1.0659x over previous
#include <cuda_runtime.h>
#include <cstdint>

#define N_NODES 200000
#define NB1 3125            // 64-row tiles for K1/K3
#define NB2 1563            // 128-row tiles for K2
#define EPS_BN 1e-3f

typedef unsigned long long ull;

// ---------------- scratch (device globals; no allocations allowed) ----------
__device__ __align__(16) float    g_y1 [N_NODES * 64];   // x @ W1 (pre-BN)
__device__ __align__(16) uint32_t g_y1t[N_NODES * 64];   // relu(bn1(y1)), tf32, col-permuted
__device__ __align__(16) float    g_y2 [N_NODES * 64];   // conv2 out (pre-BN)
__device__ __align__(16) float    g_z  [N_NODES * 256];  // h2 @ W3 (pre-BN)
__device__ float g_part1[NB1 * 128];
__device__ float g_part2[NB2 * 128];
__device__ float g_part3[NB1 * 512];
__device__ float g_sc1[64],  g_sh1[64];
__device__ float g_sc2[64],  g_sh2[64];
__device__ float g_sc3[256], g_sh3[256];
__device__ __align__(16) uint32_t g_w2t[27 * 4096];      // W2^T, tf32, col-permuted

// ---------------- helpers ---------------------------------------------------
__device__ __forceinline__ ull pack2(float x) {
    ull r; asm("mov.b64 %0, {%1, %1};" : "=l"(r) : "f"(x)); return r;
}
__device__ __forceinline__ void fma2(ull& d, ull a, ull b) {
    asm("fma.rn.f32x2 %0, %1, %2, %0;" : "+l"(d) : "l"(a), "l"(b));
}
__device__ __forceinline__ float2 unpk(ull v) {
    float2 r; asm("mov.b64 {%0, %1}, %2;" : "=f"(r.x), "=f"(r.y) : "l"(v)); return r;
}
__device__ __forceinline__ uint32_t to_tf32(float v) {
    uint32_t u; asm("cvt.rna.tf32.f32 %0, %1;" : "=r"(u) : "f"(v)); return u;
}
__device__ __forceinline__ uint32_t smem_u32(const void* p) {
    uint32_t a; asm("{ .reg .u64 t; cvta.to.shared.u64 t, %1; cvt.u32.u64 %0, t; }"
                    : "=r"(a) : "l"(p));
    return a;
}
__device__ __forceinline__ void mma_tf32(float* c,
    uint32_t a0, uint32_t a1, uint32_t a2, uint32_t a3, uint32_t b0, uint32_t b1)
{
    asm volatile(
        "mma.sync.aligned.m16n8k8.row.col.f32.tf32.tf32.f32 "
        "{%0,%1,%2,%3}, {%4,%5,%6,%7}, {%8,%9}, {%0,%1,%2,%3};"
        : "+f"(c[0]), "+f"(c[1]), "+f"(c[2]), "+f"(c[3])
        : "r"(a0), "r"(a1), "r"(a2), "r"(a3), "r"(b0), "r"(b1));
}
__device__ __forceinline__ void cp16(uint32_t dst, const void* src) {
    asm volatile("cp.async.cg.shared.global [%0], [%1], 16;" :: "r"(dst), "l"(src));
}
__device__ __forceinline__ void cp16p(uint32_t dst, const void* src, int ssz) {
    asm volatile("cp.async.cg.shared.global [%0], [%1], 16, %2;"
                 :: "r"(dst), "l"(src), "r"(ssz));
}

// ---------------- shared epilogue for SIMT GEMMs (K1/K3) --------------------
__device__ __forceinline__ void epilogue_store_stats(
    ull acc[4][4], float* ybuf, int ypitch, int row0, int col0,
    float* red, float* psum_out, float* psq_out, int tx, int ty, int tid)
{
    float ps[8], pq[8];
#pragma unroll
    for (int u = 0; u < 8; u++) { ps[u] = 0.f; pq[u] = 0.f; }
#pragma unroll
    for (int i = 0; i < 4; i++) {
        int row = row0 + ty + 16 * i;
#pragma unroll
        for (int j = 0; j < 4; j++) {
            float2 v = unpk(acc[i][j]);
            *(float2*)&ybuf[(size_t)row * ypitch + col0 + 2 * (tx + 8 * j)] = v;
            ps[2 * j]     += v.x;  pq[2 * j]     += v.x * v.x;
            ps[2 * j + 1] += v.y;  pq[2 * j + 1] += v.y * v.y;
        }
    }
    __syncthreads();
#pragma unroll
    for (int j = 0; j < 4; j++) {
        red[ty * 64 + 2 * (tx + 8 * j)]     = ps[2 * j];
        red[ty * 64 + 2 * (tx + 8 * j) + 1] = ps[2 * j + 1];
    }
    __syncthreads();
    if (tid < 64) {
        float s = 0.f;
#pragma unroll
        for (int t = 0; t < 16; t++) s += red[t * 64 + tid];
        psum_out[tid] = s;
    }
    __syncthreads();
#pragma unroll
    for (int j = 0; j < 4; j++) {
        red[ty * 64 + 2 * (tx + 8 * j)]     = pq[2 * j];
        red[ty * 64 + 2 * (tx + 8 * j) + 1] = pq[2 * j + 1];
    }
    __syncthreads();
    if (tid < 64) {
        float s = 0.f;
#pragma unroll
        for (int t = 0; t < 16; t++) s += red[t * 64 + tid];
        psq_out[tid] = s;
    }
}

// ---------------- K1: y1 = x @ W1  (SIMT f32x2) -----------------------------
__global__ __launch_bounds__(128) void k1_gemm(
    const float* __restrict__ x, const float* __restrict__ W1)
{
    __shared__ __align__(16) float x_s[64 * 32];
    __shared__ __align__(16) float w_s[32 * 64];
    int tid = threadIdx.x, tx = tid & 7, ty = tid >> 3;
    int bid = blockIdx.x, row0 = bid * 64;

    ull acc[4][4];
#pragma unroll
    for (int i = 0; i < 4; i++)
#pragma unroll
        for (int j = 0; j < 4; j++) acc[i][j] = 0ull;

    for (int kk = 0; kk < 256; kk += 32) {
#pragma unroll
        for (int q = 0; q < 4; q++) {
            int fi = tid + q * 128; int r = fi >> 3, c4 = fi & 7;
            *(float4*)&x_s[r * 32 + c4 * 4] =
                *(const float4*)&x[(size_t)(row0 + r) * 256 + kk + c4 * 4];
        }
#pragma unroll
        for (int q = 0; q < 4; q++) {
            int fi = tid + q * 128; int r = fi >> 4, c4 = fi & 15;
            *(float4*)&w_s[r * 64 + c4 * 4] =
                *(const float4*)&W1[(size_t)(kk + r) * 64 + c4 * 4];
        }
        __syncthreads();
#pragma unroll
        for (int c = 0; c < 32; c++) {
            ull av0 = pack2(x_s[ ty       * 32 + c]);
            ull av1 = pack2(x_s[(ty + 16) * 32 + c]);
            ull av2 = pack2(x_s[(ty + 32) * 32 + c]);
            ull av3 = pack2(x_s[(ty + 48) * 32 + c]);
#pragma unroll
            for (int j = 0; j < 4; j++) {
                ull wv = *(const ull*)&w_s[c * 64 + 2 * (tx + 8 * j)];
                fma2(acc[0][j], av0, wv);
                fma2(acc[1][j], av1, wv);
                fma2(acc[2][j], av2, wv);
                fma2(acc[3][j], av3, wv);
            }
        }
        __syncthreads();
    }
    epilogue_store_stats(acc, g_y1, 64, row0, 0, x_s,
                         g_part1 + bid * 128, g_part1 + bid * 128 + 64,
                         tx, ty, tid);
}

// ---------------- BN finalize body ------------------------------------------
__device__ __forceinline__ void fin_body(
    const float* part, int nb, int C, const float* gamma, const float* beta,
    float* sc, float* sh)
{
    __shared__ float ss[256], sq[256];
    int c = blockIdx.x, t = threadIdx.x;
    float s = 0.f, q = 0.f;
    for (int b = t; b < nb; b += 256) {
        s += part[(size_t)b * 2 * C + c];
        q += part[(size_t)b * 2 * C + C + c];
    }
    ss[t] = s; sq[t] = q; __syncthreads();
    for (int d = 128; d; d >>= 1) {
        if (t < d) { ss[t] += ss[t + d]; sq[t] += sq[t + d]; }
        __syncthreads();
    }
    if (t == 0) {
        float mean = ss[0] / (float)N_NODES;
        float var  = sq[0] / (float)N_NODES - mean * mean;
        float r = rsqrtf(var + EPS_BN);
        float scale = gamma[c] * r;
        sc[c] = scale;
        sh[c] = beta[c] - mean * scale;
    }
}

// ---------------- f1p: BN1 finalize + W2 prep --------------------------------
__global__ void f1p(const float* g, const float* b, const float* __restrict__ W2)
{
    fin_body(g_part1, NB1, 64, g, b, g_sc1, g_sh1);
    for (int i = blockIdx.x * 256 + threadIdx.x; i < 27 * 4096; i += 64 * 256) {
        int k = i >> 12, e = i & 4095;
        int c = e >> 6, n = e & 63;
        uint32_t u = to_tf32(W2[i]);
        int p = ((c >> 3) << 3) + ((c & 3) << 1) + ((c & 7) >> 2);
        g_w2t[(size_t)k * 4096 + n * 64 + p] = u;
    }
}

// ---------------- k1b: g_y1t = permute(tf32(relu(bn1(y1)))) -----------------
__global__ __launch_bounds__(256) void k1b()
{
    size_t i = (size_t)blockIdx.x * 256 + threadIdx.x;   // float4 index
    if (i >= (size_t)N_NODES * 16) return;
    int c4 = (int)(i & 15), cb = c4 * 4;
    float4 v = *(const float4*)&g_y1[i * 4];
    uint32_t u0 = to_tf32(fmaxf(fmaf(v.x, g_sc1[cb],     g_sh1[cb]),     0.f));
    uint32_t u1 = to_tf32(fmaxf(fmaf(v.y, g_sc1[cb + 1], g_sh1[cb + 1]), 0.f));
    uint32_t u2 = to_tf32(fmaxf(fmaf(v.z, g_sc1[cb + 2], g_sh1[cb + 2]), 0.f));
    uint32_t u3 = to_tf32(fmaxf(fmaf(v.w, g_sc1[cb + 3], g_sh1[cb + 3]), 0.f));
    int grp = c4 >> 1, odd = c4 & 1;
    uint32_t* dst = g_y1t + (i >> 4) * 64 + grp * 8 + odd;
    dst[0] = u0; dst[2] = u1; dst[4] = u2; dst[6] = u3;
}

// ---------------- K2: tf32 mma.sync gather-GEMM, cp.async 2-stage, occ=2 ----
// 256 thr / 8 warps; 128 rows x 64 cols per CTA.
// Warp grid 4x2: warp w -> rows (w>>1)*32..+32, cols (w&1)*32..+32.
// No smem index staging: per-thread register prefetch of neighbor indices.
#define K2_AS   0        // word offsets: A 2 x 128 x 68
#define K2_BS   17408    // B 2 x 64 x 68
#define K2_PS   26112    // 4 x 64
#define K2_PQ   26368    // 4 x 64
#define K2_U32  26624    // 106496 bytes -> 2 CTAs / SM

__device__ __forceinline__ void k2_issue(
    uint32_t sbase, int tid, int grow, int h, int gvalid, int gi,
    int k, int buf)
{
    // B tile: 64 rows x 16 uint4, 4 per thread
    const char* bs = (const char*)(g_w2t + (size_t)k * 4096);
#pragma unroll
    for (int q = 0; q < 4; q++) {
        int e = tid + q * 256, n = e >> 4, w = e & 15;
        cp16(sbase + (K2_BS + buf * 4352 + n * 68 + w * 4) * 4,
             bs + (n * 64 + w * 4) * 4);
    }
    // A gather: half-row (8 uint4) per thread
    const char* as = (const char*)(g_y1t + (size_t)gi * 64 + h * 4);
    uint32_t dst = sbase + (K2_AS + buf * 8704 + grow * 68 + h * 4) * 4;
    int ssz = gvalid ? 16 : 0;
#pragma unroll
    for (int q = 0; q < 8; q++)
        cp16p(dst + q * 16, as + q * 16, ssz);
    asm volatile("cp.async.commit_group;" ::: "memory");
}

__global__ __launch_bounds__(256, 2) void k2_tc(const int* __restrict__ neigh)
{
    extern __shared__ uint32_t dsm[];
    uint32_t sbase = smem_u32(dsm);
    float* psum = (float*)(dsm + K2_PS);
    float* psq  = (float*)(dsm + K2_PQ);

    int tid = threadIdx.x, wid = tid >> 5, lane = tid & 31;
    int g = lane >> 2, t = lane & 3;
    int rg = wid >> 1, cg = wid & 1;
    int bid = blockIdx.x, row0 = bid * 128;
    int nval = N_NODES - row0; if (nval > 128) nval = 128;

    int grow = tid >> 1;
    int h    = (tid & 1) * 8;
    int gvalid = grow < nval;
    const int* nrow = neigh + (size_t)(row0 + (gvalid ? grow : 0)) * 27;

    float acc[2][4][4];
#pragma unroll
    for (int i = 0; i < 2; i++)
#pragma unroll
        for (int j = 0; j < 4; j++)
#pragma unroll
            for (int u = 0; u < 4; u++) acc[i][j][u] = 0.f;

    int idx_cur  = gvalid ? nrow[0] : 0;
    int idx_next = gvalid ? nrow[1] : 0;
    k2_issue(sbase, tid, grow, h, gvalid, idx_cur, 0, 0);

    int ra0 = rg * 32 + g;
    for (int k = 0; k < 27; k++) {
        int buf = k & 1;
        asm volatile("cp.async.wait_group 0;" ::: "memory");
        __syncthreads();
        if (k + 1 < 27) {
            k2_issue(sbase, tid, grow, h, gvalid, idx_next, k + 1, buf ^ 1);
            idx_next = (gvalid && k + 2 < 27) ? nrow[k + 2] : 0;  // overlaps compute
        }
        const uint32_t* As = dsm + K2_AS + buf * 8704;
        const uint32_t* Bs = dsm + K2_BS + buf * 4352;
#pragma unroll
        for (int kk = 0; kk < 8; kk++) {
            int co = kk * 8 + t * 2;
            uint2 a00 = *(const uint2*)&As[(ra0     ) * 68 + co];
            uint2 a01 = *(const uint2*)&As[(ra0 +  8) * 68 + co];
            uint2 a10 = *(const uint2*)&As[(ra0 + 16) * 68 + co];
            uint2 a11 = *(const uint2*)&As[(ra0 + 24) * 68 + co];
#pragma unroll
            for (int j = 0; j < 4; j++) {
                int nt = cg * 4 + j;
                uint2 b = *(const uint2*)&Bs[(nt * 8 + g) * 68 + co];
                mma_tf32(acc[0][j], a00.x, a01.x, a00.y, a01.y, b.x, b.y);
                mma_tf32(acc[1][j], a10.x, a11.x, a10.y, a11.y, b.x, b.y);
            }
        }
    }

    // epilogue: store y2 + BN2 stat partials
    int rbase = row0 + rg * 32 + g;
#pragma unroll
    for (int j = 0; j < 4; j++) {
        int col = cg * 32 + j * 8 + t * 2;
        float s0 = 0.f, s1 = 0.f, q0 = 0.f, q1 = 0.f;
#pragma unroll
        for (int i = 0; i < 2; i++) {
            float c0 = acc[i][j][0], c1 = acc[i][j][1];
            float c2 = acc[i][j][2], c3 = acc[i][j][3];
            int rowA = rbase + i * 16, rowB = rowA + 8;
            if (rowA < N_NODES) {
                float2 v; v.x = c0; v.y = c1;
                *(float2*)&g_y2[(size_t)rowA * 64 + col] = v;
            }
            if (rowB < N_NODES) {
                float2 v; v.x = c2; v.y = c3;
                *(float2*)&g_y2[(size_t)rowB * 64 + col] = v;
            }
            s0 += c0 + c2;  s1 += c1 + c3;
            q0 += c0 * c0 + c2 * c2;  q1 += c1 * c1 + c3 * c3;
        }
#pragma unroll
        for (int d = 4; d <= 16; d <<= 1) {
            s0 += __shfl_xor_sync(0xFFFFFFFFu, s0, d);
            s1 += __shfl_xor_sync(0xFFFFFFFFu, s1, d);
            q0 += __shfl_xor_sync(0xFFFFFFFFu, q0, d);
            q1 += __shfl_xor_sync(0xFFFFFFFFu, q1, d);
        }
        if (g == 0) {
            psum[rg * 64 + col]     = s0;
            psum[rg * 64 + col + 1] = s1;
            psq [rg * 64 + col]     = q0;
            psq [rg * 64 + col + 1] = q1;
        }
    }
    __syncthreads();
    if (tid < 64) {
        float s = 0.f, q = 0.f;
#pragma unroll
        for (int w = 0; w < 4; w++) { s += psum[w * 64 + tid]; q += psq[w * 64 + tid]; }
        g_part2[bid * 128 + tid]      = s;
        g_part2[bid * 128 + 64 + tid] = q;
    }
}

// ---------------- K3: z = relu(bn2(y2)) @ W3 (SIMT f32x2) -------------------
__global__ __launch_bounds__(128) void k3_gemm(const float* __restrict__ W3)
{
    __shared__ __align__(16) float a_s[64 * 64];
    __shared__ __align__(16) float w_s[64 * 64];
    int tid = threadIdx.x, tx = tid & 7, ty = tid >> 3;
    int bid = blockIdx.x, cb = blockIdx.y;
    int row0 = bid * 64, col0 = cb * 64;

#pragma unroll
    for (int q = 0; q < 8; q++) {
        int fi = tid + q * 128; int r = fi >> 4, c4 = fi & 15; int c0 = c4 * 4;
        float4 v = *(const float4*)&g_y2[(size_t)(row0 + r) * 64 + c0];
        v.x = fmaxf(fmaf(v.x, g_sc2[c0],     g_sh2[c0]),     0.f);
        v.y = fmaxf(fmaf(v.y, g_sc2[c0 + 1], g_sh2[c0 + 1]), 0.f);
        v.z = fmaxf(fmaf(v.z, g_sc2[c0 + 2], g_sh2[c0 + 2]), 0.f);
        v.w = fmaxf(fmaf(v.w, g_sc2[c0 + 3], g_sh2[c0 + 3]), 0.f);
        *(float4*)&a_s[r * 64 + c0] = v;
    }
#pragma unroll
    for (int q = 0; q < 8; q++) {
        int fi = tid + q * 128; int r = fi >> 4, c4 = fi & 15;
        *(float4*)&w_s[r * 64 + c4 * 4] =
            *(const float4*)&W3[(size_t)r * 256 + col0 + c4 * 4];
    }
    __syncthreads();

    ull acc[4][4];
#pragma unroll
    for (int i = 0; i < 4; i++)
#pragma unroll
        for (int j = 0; j < 4; j++) acc[i][j] = 0ull;

#pragma unroll 8
    for (int c = 0; c < 64; c++) {
        ull av0 = pack2(a_s[ ty       * 64 + c]);
        ull av1 = pack2(a_s[(ty + 16) * 64 + c]);
        ull av2 = pack2(a_s[(ty + 32) * 64 + c]);
        ull av3 = pack2(a_s[(ty + 48) * 64 + c]);
#pragma unroll
        for (int j = 0; j < 4; j++) {
            ull wv = *(const ull*)&w_s[c * 64 + 2 * (tx + 8 * j)];
            fma2(acc[0][j], av0, wv);
            fma2(acc[1][j], av1, wv);
            fma2(acc[2][j], av2, wv);
            fma2(acc[3][j], av3, wv);
        }
    }
    epilogue_store_stats(acc, g_z, 256, row0, col0, a_s,
                         g_part3 + (size_t)bid * 512 + col0,
                         g_part3 + (size_t)bid * 512 + 256 + col0,
                         tx, ty, tid);
}

__global__ void f2k(const float* g, const float* b) { fin_body(g_part2, NB2,  64, g, b, g_sc2, g_sh2); }
__global__ void f3k(const float* g, const float* b) { fin_body(g_part3, NB1, 256, g, b, g_sc3, g_sh3); }

// ---------------- K4: out = relu(bn3(z) + x) --------------------------------
__global__ __launch_bounds__(256) void k4_out(
    const float* __restrict__ x, float* __restrict__ out)
{
    int i = blockIdx.x * 256 + threadIdx.x;
    if (i >= N_NODES * 64) return;
    int c0 = (i & 63) * 4;
    float4 z  = *(const float4*)&g_z[(size_t)i * 4];
    float4 xv = *(const float4*)&x  [(size_t)i * 4];
    float4 o;
    o.x = fmaxf(fmaf(z.x, g_sc3[c0],     g_sh3[c0])     + xv.x, 0.f);
    o.y = fmaxf(fmaf(z.y, g_sc3[c0 + 1], g_sh3[c0 + 1]) + xv.y, 0.f);
    o.z = fmaxf(fmaf(z.z, g_sc3[c0 + 2], g_sh3[c0 + 2]) + xv.z, 0.f);
    o.w = fmaxf(fmaf(z.w, g_sc3[c0 + 3], g_sh3[c0 + 3]) + xv.w, 0.f);
    *(float4*)&out[(size_t)i * 4] = o;
}

// ---------------- launch ---------------------------------------------------
extern "C" void kernel_launch(void* const* d_in, const int* in_sizes, int n_in,
                              void* d_out, int out_size)
{
    const float* x     = (const float*)d_in[0];
    const int*   neigh = (const int*)  d_in[1];
    const float* W1 = (const float*)d_in[3];
    const float* g1 = (const float*)d_in[4];
    const float* b1 = (const float*)d_in[5];
    const float* W2 = (const float*)d_in[6];
    const float* g2 = (const float*)d_in[7];
    const float* b2 = (const float*)d_in[8];
    const float* W3 = (const float*)d_in[9];
    const float* g3 = (const float*)d_in[10];
    const float* b3 = (const float*)d_in[11];
    float* out = (float*)d_out;

    cudaFuncSetAttribute(k2_tc, cudaFuncAttributeMaxDynamicSharedMemorySize,
                         K2_U32 * 4);

    k1_gemm<<<NB1, 128>>>(x, W1);                       // launch 1
    f1p<<<64, 256>>>(g1, b1, W2);                       // launch 2 (BN1 + W2 prep)
    k1b<<<(N_NODES * 16 + 255) / 256, 256>>>();         // launch 3
    k2_tc<<<NB2, 256, K2_U32 * 4>>>(neigh);             // launch 4 (profiled slot)
    f2k<<<64, 256>>>(g2, b2);                           // launch 5
    k3_gemm<<<dim3(NB1, 4), 128>>>(W3);                 // launch 6
    f3k<<<256, 256>>>(g3, b3);                          // launch 7
    k4_out<<<(N_NODES * 64 + 255) / 256, 256>>>(x, out);// launch 8
}

// round 14
// speedup vs baseline: 1.6468x; 1.1170x over previous
#include <cuda_runtime.h>
#include <cstdint>

#define N_NODES 200000
#define NB1 3125            // 64-row tiles for K1/K3
#define NB2 1563            // 128-row tiles for K2
#define EPS_BN 1e-3f

typedef unsigned long long ull;

// ---------------- scratch (device globals; no allocations allowed) ----------
__device__ __align__(16) float    g_y1 [N_NODES * 64];   // x @ W1 (pre-BN)
__device__ __align__(16) uint32_t g_y1t[N_NODES * 64];   // relu(bn1(y1)), tf32, p2-permuted
__device__ __align__(16) float    g_y2 [N_NODES * 64];   // conv2 out (pre-BN)
__device__ __align__(16) float    g_z  [N_NODES * 256];  // h2 @ W3 (pre-BN)
__device__ float g_part1[NB1 * 128];
__device__ float g_part2[NB2 * 128];
__device__ float g_part3[NB1 * 512];
__device__ float g_sc1[64],  g_sh1[64];
__device__ float g_sc2[64],  g_sh2[64];
__device__ float g_sc3[256], g_sh3[256];
__device__ __align__(16) uint32_t g_w2t[27 * 4096];      // W2^T, tf32, p2-permuted

// ---------------- helpers ---------------------------------------------------
__device__ __forceinline__ ull pack2(float x) {
    ull r; asm("mov.b64 %0, {%1, %1};" : "=l"(r) : "f"(x)); return r;
}
__device__ __forceinline__ void fma2(ull& d, ull a, ull b) {
    asm("fma.rn.f32x2 %0, %1, %2, %0;" : "+l"(d) : "l"(a), "l"(b));
}
__device__ __forceinline__ float2 unpk(ull v) {
    float2 r; asm("mov.b64 {%0, %1}, %2;" : "=f"(r.x), "=f"(r.y) : "l"(v)); return r;
}
__device__ __forceinline__ uint32_t to_tf32(float v) {
    uint32_t u; asm("cvt.rna.tf32.f32 %0, %1;" : "=r"(u) : "f"(v)); return u;
}
__device__ __forceinline__ uint32_t smem_u32(const void* p) {
    uint32_t a; asm("{ .reg .u64 t; cvta.to.shared.u64 t, %1; cvt.u32.u64 %0, t; }"
                    : "=r"(a) : "l"(p));
    return a;
}
__device__ __forceinline__ void mma_tf32(float* c,
    uint32_t a0, uint32_t a1, uint32_t a2, uint32_t a3, uint32_t b0, uint32_t b1)
{
    asm volatile(
        "mma.sync.aligned.m16n8k8.row.col.f32.tf32.tf32.f32 "
        "{%0,%1,%2,%3}, {%4,%5,%6,%7}, {%8,%9}, {%0,%1,%2,%3};"
        : "+f"(c[0]), "+f"(c[1]), "+f"(c[2]), "+f"(c[3])
        : "r"(a0), "r"(a1), "r"(a2), "r"(a3), "r"(b0), "r"(b1));
}
__device__ __forceinline__ void cp16(uint32_t dst, const void* src) {
    asm volatile("cp.async.cg.shared.global [%0], [%1], 16;" :: "r"(dst), "l"(src));
}
__device__ __forceinline__ void cp16p(uint32_t dst, const void* src, int ssz) {
    asm volatile("cp.async.cg.shared.global [%0], [%1], 16, %2;"
                 :: "r"(dst), "l"(src), "r"(ssz));
}

// ---------------- shared epilogue for SIMT GEMMs (K1/K3) --------------------
__device__ __forceinline__ void epilogue_store_stats(
    ull acc[4][4], float* ybuf, int ypitch, int row0, int col0,
    float* red, float* psum_out, float* psq_out, int tx, int ty, int tid)
{
    float ps[8], pq[8];
#pragma unroll
    for (int u = 0; u < 8; u++) { ps[u] = 0.f; pq[u] = 0.f; }
#pragma unroll
    for (int i = 0; i < 4; i++) {
        int row = row0 + ty + 16 * i;
#pragma unroll
        for (int j = 0; j < 4; j++) {
            float2 v = unpk(acc[i][j]);
            *(float2*)&ybuf[(size_t)row * ypitch + col0 + 2 * (tx + 8 * j)] = v;
            ps[2 * j]     += v.x;  pq[2 * j]     += v.x * v.x;
            ps[2 * j + 1] += v.y;  pq[2 * j + 1] += v.y * v.y;
        }
    }
    __syncthreads();
#pragma unroll
    for (int j = 0; j < 4; j++) {
        red[ty * 64 + 2 * (tx + 8 * j)]     = ps[2 * j];
        red[ty * 64 + 2 * (tx + 8 * j) + 1] = ps[2 * j + 1];
    }
    __syncthreads();
    if (tid < 64) {
        float s = 0.f;
#pragma unroll
        for (int t = 0; t < 16; t++) s += red[t * 64 + tid];
        psum_out[tid] = s;
    }
    __syncthreads();
#pragma unroll
    for (int j = 0; j < 4; j++) {
        red[ty * 64 + 2 * (tx + 8 * j)]     = pq[2 * j];
        red[ty * 64 + 2 * (tx + 8 * j) + 1] = pq[2 * j + 1];
    }
    __syncthreads();
    if (tid < 64) {
        float s = 0.f;
#pragma unroll
        for (int t = 0; t < 16; t++) s += red[t * 64 + tid];
        psq_out[tid] = s;
    }
}

// ---------------- K1: y1 = x @ W1  (SIMT f32x2) -----------------------------
__global__ __launch_bounds__(128) void k1_gemm(
    const float* __restrict__ x, const float* __restrict__ W1)
{
    __shared__ __align__(16) float x_s[64 * 32];
    __shared__ __align__(16) float w_s[32 * 64];
    int tid = threadIdx.x, tx = tid & 7, ty = tid >> 3;
    int bid = blockIdx.x, row0 = bid * 64;

    ull acc[4][4];
#pragma unroll
    for (int i = 0; i < 4; i++)
#pragma unroll
        for (int j = 0; j < 4; j++) acc[i][j] = 0ull;

    for (int kk = 0; kk < 256; kk += 32) {
#pragma unroll
        for (int q = 0; q < 4; q++) {
            int fi = tid + q * 128; int r = fi >> 3, c4 = fi & 7;
            *(float4*)&x_s[r * 32 + c4 * 4] =
                *(const float4*)&x[(size_t)(row0 + r) * 256 + kk + c4 * 4];
        }
#pragma unroll
        for (int q = 0; q < 4; q++) {
            int fi = tid + q * 128; int r = fi >> 4, c4 = fi & 15;
            *(float4*)&w_s[r * 64 + c4 * 4] =
                *(const float4*)&W1[(size_t)(kk + r) * 64 + c4 * 4];
        }
        __syncthreads();
#pragma unroll
        for (int c = 0; c < 32; c++) {
            ull av0 = pack2(x_s[ ty       * 32 + c]);
            ull av1 = pack2(x_s[(ty + 16) * 32 + c]);
            ull av2 = pack2(x_s[(ty + 32) * 32 + c]);
            ull av3 = pack2(x_s[(ty + 48) * 32 + c]);
#pragma unroll
            for (int j = 0; j < 4; j++) {
                ull wv = *(const ull*)&w_s[c * 64 + 2 * (tx + 8 * j)];
                fma2(acc[0][j], av0, wv);
                fma2(acc[1][j], av1, wv);
                fma2(acc[2][j], av2, wv);
                fma2(acc[3][j], av3, wv);
            }
        }
        __syncthreads();
    }
    epilogue_store_stats(acc, g_y1, 64, row0, 0, x_s,
                         g_part1 + bid * 128, g_part1 + bid * 128 + 64,
                         tx, ty, tid);
}

// ---------------- BN finalize body ------------------------------------------
__device__ __forceinline__ void fin_body(
    const float* part, int nb, int C, const float* gamma, const float* beta,
    float* sc, float* sh)
{
    __shared__ float ss[256], sq[256];
    int c = blockIdx.x, t = threadIdx.x;
    float s = 0.f, q = 0.f;
    for (int b = t; b < nb; b += 256) {
        s += part[(size_t)b * 2 * C + c];
        q += part[(size_t)b * 2 * C + C + c];
    }
    ss[t] = s; sq[t] = q; __syncthreads();
    for (int d = 128; d; d >>= 1) {
        if (t < d) { ss[t] += ss[t + d]; sq[t] += sq[t + d]; }
        __syncthreads();
    }
    if (t == 0) {
        float mean = ss[0] / (float)N_NODES;
        float var  = sq[0] / (float)N_NODES - mean * mean;
        float r = rsqrtf(var + EPS_BN);
        float scale = gamma[c] * r;
        sc[c] = scale;
        sh[c] = beta[c] - mean * scale;
    }
}

// p2 channel permutation: chans (kk*8+t, kk*8+t+4) of a kk-pair -> one 16B chunk
// p2(c) = (c&48) + 4*(c&3) + ((c&15)>>2)

// ---------------- f1p: BN1 finalize + W2 prep --------------------------------
__global__ void f1p(const float* g, const float* b, const float* __restrict__ W2)
{
    fin_body(g_part1, NB1, 64, g, b, g_sc1, g_sh1);
    for (int i = blockIdx.x * 256 + threadIdx.x; i < 27 * 4096; i += 64 * 256) {
        int k = i >> 12, e = i & 4095;
        int c = e >> 6, n = e & 63;
        uint32_t u = to_tf32(W2[i]);
        int p = (c & 48) + ((c & 3) << 2) + ((c & 15) >> 2);
        g_w2t[(size_t)k * 4096 + n * 64 + p] = u;
    }
}

// ---------------- k1b: g_y1t = p2-permute(tf32(relu(bn1(y1)))) --------------
__global__ __launch_bounds__(256) void k1b()
{
    size_t i = (size_t)blockIdx.x * 256 + threadIdx.x;   // float4 index
    if (i >= (size_t)N_NODES * 16) return;
    int c4 = (int)(i & 15), cb = c4 * 4;
    float4 v = *(const float4*)&g_y1[i * 4];
    uint32_t u0 = to_tf32(fmaxf(fmaf(v.x, g_sc1[cb],     g_sh1[cb]),     0.f));
    uint32_t u1 = to_tf32(fmaxf(fmaf(v.y, g_sc1[cb + 1], g_sh1[cb + 1]), 0.f));
    uint32_t u2 = to_tf32(fmaxf(fmaf(v.z, g_sc1[cb + 2], g_sh1[cb + 2]), 0.f));
    uint32_t u3 = to_tf32(fmaxf(fmaf(v.w, g_sc1[cb + 3], g_sh1[cb + 3]), 0.f));
    // p2(cb+i) = (cb&48) + 4i + ((cb&15)>>2)
    int base = (cb & 48) + ((cb & 15) >> 2);
    uint32_t* dst = g_y1t + (i >> 4) * 64 + base;
    dst[0] = u0; dst[4] = u1; dst[8] = u2; dst[12] = u3;
}

// ---------------- K2: tf32 mma.sync gather-GEMM -----------------------------
// 256 thr / 8 warps; 128 rows x 64 cols per CTA; 2 CTAs/SM.
// Conflict-free smem: 64-word rows, chunk-swizzle off ^= (row&1)<<4.
// All fragment loads are LDS.128 (kk-pair packed via p2 permutation).
#define K2_AS   0        // word offsets: A 2 x 128 x 64
#define K2_BS   16384    // B 2 x 64 x 64
#define K2_PS   24576    // 4 x 64
#define K2_PQ   24832    // 4 x 64
#define K2_U32  25088    // 100352 bytes -> 2 CTAs / SM

__device__ __forceinline__ void k2_issue(
    uint32_t sbase, int tid, int grow, int cI0, int gvalid, int gi,
    int k, int buf)
{
    // B tile: 64 rows x 16 chunks, 4 per thread (swizzled dst)
    const char* bs = (const char*)(g_w2t + (size_t)k * 4096);
#pragma unroll
    for (int q = 0; q < 4; q++) {
        int e = tid + q * 256, n = e >> 4, cI = e & 15;
        uint32_t dw = K2_BS + buf * 4096 + n * 64 + (((uint32_t)cI * 4) ^ ((n & 1) << 4));
        cp16(sbase + dw * 4, bs + e * 16);
    }
    // A gather: half-row (8 chunks) per thread (swizzled dst)
    const char* as = (const char*)(g_y1t + (size_t)gi * 64 + cI0 * 4);
    int ssz = gvalid ? 16 : 0;
    uint32_t rbase = K2_AS + buf * 8192 + grow * 64;
    uint32_t rx = (grow & 1) << 4;
#pragma unroll
    for (int q = 0; q < 8; q++) {
        uint32_t dw = rbase + ((((uint32_t)(cI0 + q)) * 4) ^ rx);
        cp16p(sbase + dw * 4, as + q * 16, ssz);
    }
    asm volatile("cp.async.commit_group;" ::: "memory");
}

__global__ __launch_bounds__(256, 2) void k2_tc(const int* __restrict__ neigh)
{
    extern __shared__ uint32_t dsm[];
    uint32_t sbase = smem_u32(dsm);
    float* psum = (float*)(dsm + K2_PS);
    float* psq  = (float*)(dsm + K2_PQ);

    int tid = threadIdx.x, wid = tid >> 5, lane = tid & 31;
    int g = lane >> 2, t = lane & 3;
    int rg = wid >> 1, cg = wid & 1;
    int bid = blockIdx.x, row0 = bid * 128;
    int nval = N_NODES - row0; if (nval > 128) nval = 128;

    int grow = tid >> 1;
    int cI0  = (tid & 1) * 8;
    int gvalid = grow < nval;
    const int* nrow = neigh + (size_t)(row0 + (gvalid ? grow : 0)) * 27;

    float acc[2][4][4];
#pragma unroll
    for (int i = 0; i < 2; i++)
#pragma unroll
        for (int j = 0; j < 4; j++)
#pragma unroll
            for (int u = 0; u < 4; u++) acc[i][j][u] = 0.f;

    int idx_cur  = gvalid ? nrow[0] : 0;
    int idx_next = gvalid ? nrow[1] : 0;
    k2_issue(sbase, tid, grow, cI0, gvalid, idx_cur, 0, 0);

    int ra0 = rg * 32 + g;
    uint32_t gx = (g & 1) << 4;        // row-parity swizzle for all frag loads
    for (int k = 0; k < 27; k++) {
        int buf = k & 1;
        asm volatile("cp.async.wait_group 0;" ::: "memory");
        __syncthreads();
        if (k + 1 < 27) {
            k2_issue(sbase, tid, grow, cI0, gvalid, idx_next, k + 1, buf ^ 1);
            idx_next = (gvalid && k + 2 < 27) ? nrow[k + 2] : 0;  // overlaps compute
        }
        const uint32_t* As = dsm + K2_AS + buf * 8192;
        const uint32_t* Bs = dsm + K2_BS + buf * 4096;
#pragma unroll
        for (int kkp = 0; kkp < 4; kkp++) {
            uint32_t off = (uint32_t)(kkp * 16 + t * 4) ^ gx;
            uint4 a00 = *(const uint4*)&As[(ra0     ) * 64 + off];
            uint4 a01 = *(const uint4*)&As[(ra0 +  8) * 64 + off];
            uint4 a10 = *(const uint4*)&As[(ra0 + 16) * 64 + off];
            uint4 a11 = *(const uint4*)&As[(ra0 + 24) * 64 + off];
#pragma unroll
            for (int j = 0; j < 4; j++) {
                int nt = cg * 4 + j;
                uint4 b = *(const uint4*)&Bs[(nt * 8 + g) * 64 + off];
                mma_tf32(acc[0][j], a00.x, a01.x, a00.y, a01.y, b.x, b.y);
                mma_tf32(acc[0][j], a00.z, a01.z, a00.w, a01.w, b.z, b.w);
                mma_tf32(acc[1][j], a10.x, a11.x, a10.y, a11.y, b.x, b.y);
                mma_tf32(acc[1][j], a10.z, a11.z, a10.w, a11.w, b.z, b.w);
            }
        }
    }

    // epilogue: store y2 + BN2 stat partials
    int rbase = row0 + rg * 32 + g;
#pragma unroll
    for (int j = 0; j < 4; j++) {
        int col = cg * 32 + j * 8 + t * 2;
        float s0 = 0.f, s1 = 0.f, q0 = 0.f, q1 = 0.f;
#pragma unroll
        for (int i = 0; i < 2; i++) {
            float c0 = acc[i][j][0], c1 = acc[i][j][1];
            float c2 = acc[i][j][2], c3 = acc[i][j][3];
            int rowA = rbase + i * 16, rowB = rowA + 8;
            if (rowA < N_NODES) {
                float2 v; v.x = c0; v.y = c1;
                *(float2*)&g_y2[(size_t)rowA * 64 + col] = v;
            }
            if (rowB < N_NODES) {
                float2 v; v.x = c2; v.y = c3;
                *(float2*)&g_y2[(size_t)rowB * 64 + col] = v;
            }
            s0 += c0 + c2;  s1 += c1 + c3;
            q0 += c0 * c0 + c2 * c2;  q1 += c1 * c1 + c3 * c3;
        }
#pragma unroll
        for (int d = 4; d <= 16; d <<= 1) {
            s0 += __shfl_xor_sync(0xFFFFFFFFu, s0, d);
            s1 += __shfl_xor_sync(0xFFFFFFFFu, s1, d);
            q0 += __shfl_xor_sync(0xFFFFFFFFu, q0, d);
            q1 += __shfl_xor_sync(0xFFFFFFFFu, q1, d);
        }
        if (g == 0) {
            psum[rg * 64 + col]     = s0;
            psum[rg * 64 + col + 1] = s1;
            psq [rg * 64 + col]     = q0;
            psq [rg * 64 + col + 1] = q1;
        }
    }
    __syncthreads();
    if (tid < 64) {
        float s = 0.f, q = 0.f;
#pragma unroll
        for (int w = 0; w < 4; w++) { s += psum[w * 64 + tid]; q += psq[w * 64 + tid]; }
        g_part2[bid * 128 + tid]      = s;
        g_part2[bid * 128 + 64 + tid] = q;
    }
}

// ---------------- K3: z = relu(bn2(y2)) @ W3 (SIMT f32x2) -------------------
__global__ __launch_bounds__(128) void k3_gemm(const float* __restrict__ W3)
{
    __shared__ __align__(16) float a_s[64 * 64];
    __shared__ __align__(16) float w_s[64 * 64];
    int tid = threadIdx.x, tx = tid & 7, ty = tid >> 3;
    int bid = blockIdx.x, cb = blockIdx.y;
    int row0 = bid * 64, col0 = cb * 64;

#pragma unroll
    for (int q = 0; q < 8; q++) {
        int fi = tid + q * 128; int r = fi >> 4, c4 = fi & 15; int c0 = c4 * 4;
        float4 v = *(const float4*)&g_y2[(size_t)(row0 + r) * 64 + c0];
        v.x = fmaxf(fmaf(v.x, g_sc2[c0],     g_sh2[c0]),     0.f);
        v.y = fmaxf(fmaf(v.y, g_sc2[c0 + 1], g_sh2[c0 + 1]), 0.f);
        v.z = fmaxf(fmaf(v.z, g_sc2[c0 + 2], g_sh2[c0 + 2]), 0.f);
        v.w = fmaxf(fmaf(v.w, g_sc2[c0 + 3], g_sh2[c0 + 3]), 0.f);
        *(float4*)&a_s[r * 64 + c0] = v;
    }
#pragma unroll
    for (int q = 0; q < 8; q++) {
        int fi = tid + q * 128; int r = fi >> 4, c4 = fi & 15;
        *(float4*)&w_s[r * 64 + c4 * 4] =
            *(const float4*)&W3[(size_t)r * 256 + col0 + c4 * 4];
    }
    __syncthreads();

    ull acc[4][4];
#pragma unroll
    for (int i = 0; i < 4; i++)
#pragma unroll
        for (int j = 0; j < 4; j++) acc[i][j] = 0ull;

#pragma unroll 8
    for (int c = 0; c < 64; c++) {
        ull av0 = pack2(a_s[ ty       * 64 + c]);
        ull av1 = pack2(a_s[(ty + 16) * 64 + c]);
        ull av2 = pack2(a_s[(ty + 32) * 64 + c]);
        ull av3 = pack2(a_s[(ty + 48) * 64 + c]);
#pragma unroll
        for (int j = 0; j < 4; j++) {
            ull wv = *(const ull*)&w_s[c * 64 + 2 * (tx + 8 * j)];
            fma2(acc[0][j], av0, wv);
            fma2(acc[1][j], av1, wv);
            fma2(acc[2][j], av2, wv);
            fma2(acc[3][j], av3, wv);
        }
    }
    epilogue_store_stats(acc, g_z, 256, row0, col0, a_s,
                         g_part3 + (size_t)bid * 512 + col0,
                         g_part3 + (size_t)bid * 512 + 256 + col0,
                         tx, ty, tid);
}

__global__ void f2k(const float* g, const float* b) { fin_body(g_part2, NB2,  64, g, b, g_sc2, g_sh2); }
__global__ void f3k(const float* g, const float* b) { fin_body(g_part3, NB1, 256, g, b, g_sc3, g_sh3); }

// ---------------- K4: out = relu(bn3(z) + x) --------------------------------
__global__ __launch_bounds__(256) void k4_out(
    const float* __restrict__ x, float* __restrict__ out)
{
    int i = blockIdx.x * 256 + threadIdx.x;
    if (i >= N_NODES * 64) return;
    int c0 = (i & 63) * 4;
    float4 z  = *(const float4*)&g_z[(size_t)i * 4];
    float4 xv = *(const float4*)&x  [(size_t)i * 4];
    float4 o;
    o.x = fmaxf(fmaf(z.x, g_sc3[c0],     g_sh3[c0])     + xv.x, 0.f);
    o.y = fmaxf(fmaf(z.y, g_sc3[c0 + 1], g_sh3[c0 + 1]) + xv.y, 0.f);
    o.z = fmaxf(fmaf(z.z, g_sc3[c0 + 2], g_sh3[c0 + 2]) + xv.z, 0.f);
    o.w = fmaxf(fmaf(z.w, g_sc3[c0 + 3], g_sh3[c0 + 3]) + xv.w, 0.f);
    *(float4*)&out[(size_t)i * 4] = o;
}

// ---------------- launch ---------------------------------------------------
extern "C" void kernel_launch(void* const* d_in, const int* in_sizes, int n_in,
                              void* d_out, int out_size)
{
    const float* x     = (const float*)d_in[0];
    const int*   neigh = (const int*)  d_in[1];
    const float* W1 = (const float*)d_in[3];
    const float* g1 = (const float*)d_in[4];
    const float* b1 = (const float*)d_in[5];
    const float* W2 = (const float*)d_in[6];
    const float* g2 = (const float*)d_in[7];
    const float* b2 = (const float*)d_in[8];
    const float* W3 = (const float*)d_in[9];
    const float* g3 = (const float*)d_in[10];
    const float* b3 = (const float*)d_in[11];
    float* out = (float*)d_out;

    cudaFuncSetAttribute(k2_tc, cudaFuncAttributeMaxDynamicSharedMemorySize,
                         K2_U32 * 4);

    k1_gemm<<<NB1, 128>>>(x, W1);                       // launch 1
    f1p<<<64, 256>>>(g1, b1, W2);                       // launch 2 (BN1 + W2 prep)
    k1b<<<(N_NODES * 16 + 255) / 256, 256>>>();         // launch 3
    k2_tc<<<NB2, 256, K2_U32 * 4>>>(neigh);             // launch 4 (profiled slot)
    f2k<<<64, 256>>>(g2, b2);                           // launch 5
    k3_gemm<<<dim3(NB1, 4), 128>>>(W3);                 // launch 6
    f3k<<<256, 256>>>(g3, b3);                          // launch 7
    k4_out<<<(N_NODES * 64 + 255) / 256, 256>>>(x, out);// launch 8
}

// round 16
// speedup vs baseline: 1.6772x; 1.0185x over previous
#include <cuda_runtime.h>
#include <cstdint>

#define N_NODES 200000
#define NB1 3125            // 64-row tiles for K1
#define NB2 1563            // 128-row tiles for K2/K3b
#define CB3 1184            // cov blocks
#define RPB3 169            // rows per cov block (1184*169 = 200096)
#define EPS_BN 1e-3f

typedef unsigned long long ull;

// ---------------- scratch (device globals; no allocations allowed) ----------
__device__ __align__(16) float    g_y1 [N_NODES * 64];   // x @ W1 (pre-BN)
__device__ __align__(16) uint32_t g_y1t[N_NODES * 64];   // relu(bn1(y1)), tf32, p2-perm
__device__ __align__(16) float    g_y2 [N_NODES * 64];   // conv2 out (pre-BN)
__device__ __align__(16) uint32_t g_y2t[N_NODES * 64];   // relu(bn2(y2)), tf32, p2-perm
__device__ __align__(16) float    g_z  [N_NODES * 256];  // scratch: k3a partials
__device__ float g_part1[NB1 * 128];
__device__ float g_part2[NB2 * 128];
__device__ float g_cov[4160];                            // reduced G (64x64) + m (64)
__device__ float g_sc1[64],  g_sh1[64];
__device__ float g_sc2[64],  g_sh2[64];
__device__ float g_sc3[256], g_sh3[256];
__device__ __align__(16) uint32_t g_w2t[27 * 4096];      // W2^T, tf32, p2-perm
__device__ __align__(16) uint32_t g_w3t[2 * 128 * 64];   // W3^T, tf32, p2-perm, 2 col-blocks

// ---------------- helpers ---------------------------------------------------
__device__ __forceinline__ ull pack2(float x) {
    ull r; asm("mov.b64 %0, {%1, %1};" : "=l"(r) : "f"(x)); return r;
}
__device__ __forceinline__ void fma2(ull& d, ull a, ull b) {
    asm("fma.rn.f32x2 %0, %1, %2, %0;" : "+l"(d) : "l"(a), "l"(b));
}
__device__ __forceinline__ float2 unpk(ull v) {
    float2 r; asm("mov.b64 {%0, %1}, %2;" : "=f"(r.x), "=f"(r.y) : "l"(v)); return r;
}
__device__ __forceinline__ uint32_t to_tf32(float v) {
    uint32_t u; asm("cvt.rna.tf32.f32 %0, %1;" : "=r"(u) : "f"(v)); return u;
}
__device__ __forceinline__ uint32_t smem_u32(const void* p) {
    uint32_t a; asm("{ .reg .u64 t; cvta.to.shared.u64 t, %1; cvt.u32.u64 %0, t; }"
                    : "=r"(a) : "l"(p));
    return a;
}
__device__ __forceinline__ void mma_tf32(float* c,
    uint32_t a0, uint32_t a1, uint32_t a2, uint32_t a3, uint32_t b0, uint32_t b1)
{
    asm volatile(
        "mma.sync.aligned.m16n8k8.row.col.f32.tf32.tf32.f32 "
        "{%0,%1,%2,%3}, {%4,%5,%6,%7}, {%8,%9}, {%0,%1,%2,%3};"
        : "+f"(c[0]), "+f"(c[1]), "+f"(c[2]), "+f"(c[3])
        : "r"(a0), "r"(a1), "r"(a2), "r"(a3), "r"(b0), "r"(b1));
}
__device__ __forceinline__ void cp16(uint32_t dst, const void* src) {
    asm volatile("cp.async.cg.shared.global [%0], [%1], 16;" :: "r"(dst), "l"(src));
}
__device__ __forceinline__ void cp16p(uint32_t dst, const void* src, int ssz) {
    asm volatile("cp.async.cg.shared.global [%0], [%1], 16, %2;"
                 :: "r"(dst), "l"(src), "r"(ssz));
}

// ---------------- epilogue for K1 (SIMT GEMM + stats) -----------------------
__device__ __forceinline__ void epilogue_store_stats(
    ull acc[4][4], float* ybuf, int ypitch, int row0, int col0,
    float* red, float* psum_out, float* psq_out, int tx, int ty, int tid)
{
    float ps[8], pq[8];
#pragma unroll
    for (int u = 0; u < 8; u++) { ps[u] = 0.f; pq[u] = 0.f; }
#pragma unroll
    for (int i = 0; i < 4; i++) {
        int row = row0 + ty + 16 * i;
#pragma unroll
        for (int j = 0; j < 4; j++) {
            float2 v = unpk(acc[i][j]);
            *(float2*)&ybuf[(size_t)row * ypitch + col0 + 2 * (tx + 8 * j)] = v;
            ps[2 * j]     += v.x;  pq[2 * j]     += v.x * v.x;
            ps[2 * j + 1] += v.y;  pq[2 * j + 1] += v.y * v.y;
        }
    }
    __syncthreads();
#pragma unroll
    for (int j = 0; j < 4; j++) {
        red[ty * 64 + 2 * (tx + 8 * j)]     = ps[2 * j];
        red[ty * 64 + 2 * (tx + 8 * j) + 1] = ps[2 * j + 1];
    }
    __syncthreads();
    if (tid < 64) {
        float s = 0.f;
#pragma unroll
        for (int t = 0; t < 16; t++) s += red[t * 64 + tid];
        psum_out[tid] = s;
    }
    __syncthreads();
#pragma unroll
    for (int j = 0; j < 4; j++) {
        red[ty * 64 + 2 * (tx + 8 * j)]     = pq[2 * j];
        red[ty * 64 + 2 * (tx + 8 * j) + 1] = pq[2 * j + 1];
    }
    __syncthreads();
    if (tid < 64) {
        float s = 0.f;
#pragma unroll
        for (int t = 0; t < 16; t++) s += red[t * 64 + tid];
        psq_out[tid] = s;
    }
}

// ---------------- K1: y1 = x @ W1  (SIMT f32x2) -----------------------------
__global__ __launch_bounds__(128) void k1_gemm(
    const float* __restrict__ x, const float* __restrict__ W1)
{
    __shared__ __align__(16) float x_s[64 * 32];
    __shared__ __align__(16) float w_s[32 * 64];
    int tid = threadIdx.x, tx = tid & 7, ty = tid >> 3;
    int bid = blockIdx.x, row0 = bid * 64;

    ull acc[4][4];
#pragma unroll
    for (int i = 0; i < 4; i++)
#pragma unroll
        for (int j = 0; j < 4; j++) acc[i][j] = 0ull;

    for (int kk = 0; kk < 256; kk += 32) {
#pragma unroll
        for (int q = 0; q < 4; q++) {
            int fi = tid + q * 128; int r = fi >> 3, c4 = fi & 7;
            *(float4*)&x_s[r * 32 + c4 * 4] =
                *(const float4*)&x[(size_t)(row0 + r) * 256 + kk + c4 * 4];
        }
#pragma unroll
        for (int q = 0; q < 4; q++) {
            int fi = tid + q * 128; int r = fi >> 4, c4 = fi & 15;
            *(float4*)&w_s[r * 64 + c4 * 4] =
                *(const float4*)&W1[(size_t)(kk + r) * 64 + c4 * 4];
        }
        __syncthreads();
#pragma unroll
        for (int c = 0; c < 32; c++) {
            ull av0 = pack2(x_s[ ty       * 32 + c]);
            ull av1 = pack2(x_s[(ty + 16) * 32 + c]);
            ull av2 = pack2(x_s[(ty + 32) * 32 + c]);
            ull av3 = pack2(x_s[(ty + 48) * 32 + c]);
#pragma unroll
            for (int j = 0; j < 4; j++) {
                ull wv = *(const ull*)&w_s[c * 64 + 2 * (tx + 8 * j)];
                fma2(acc[0][j], av0, wv);
                fma2(acc[1][j], av1, wv);
                fma2(acc[2][j], av2, wv);
                fma2(acc[3][j], av3, wv);
            }
        }
        __syncthreads();
    }
    epilogue_store_stats(acc, g_y1, 64, row0, 0, x_s,
                         g_part1 + bid * 128, g_part1 + bid * 128 + 64,
                         tx, ty, tid);
}

// ---------------- BN finalize body ------------------------------------------
__device__ __forceinline__ void fin_body(
    const float* part, int nb, int C, const float* gamma, const float* beta,
    float* sc, float* sh)
{
    __shared__ float ss[256], sq[256];
    int c = blockIdx.x, t = threadIdx.x;
    float s = 0.f, q = 0.f;
    for (int b = t; b < nb; b += 256) {
        s += part[(size_t)b * 2 * C + c];
        q += part[(size_t)b * 2 * C + C + c];
    }
    ss[t] = s; sq[t] = q; __syncthreads();
    for (int d = 128; d; d >>= 1) {
        if (t < d) { ss[t] += ss[t + d]; sq[t] += sq[t + d]; }
        __syncthreads();
    }
    if (t == 0) {
        float mean = ss[0] / (float)N_NODES;
        float var  = sq[0] / (float)N_NODES - mean * mean;
        float r = rsqrtf(var + EPS_BN);
        float scale = gamma[c] * r;
        sc[c] = scale;
        sh[c] = beta[c] - mean * scale;
    }
}

// p2 channel permutation: chans (kk*8+t, kk*8+t+4) of a kk-pair -> one 16B chunk
// p2(c) = (c&48) + 4*(c&3) + ((c&15)>>2)

// ---------------- f1p: BN1 finalize + W2/W3 prep -----------------------------
__global__ void f1p(const float* g, const float* b,
                    const float* __restrict__ W2, const float* __restrict__ W3)
{
    fin_body(g_part1, NB1, 64, g, b, g_sc1, g_sh1);
    for (int i = blockIdx.x * 256 + threadIdx.x; i < 27 * 4096; i += 64 * 256) {
        int k = i >> 12, e = i & 4095;
        int c = e >> 6, n = e & 63;
        uint32_t u = to_tf32(W2[i]);
        int p = (c & 48) + ((c & 3) << 2) + ((c & 15) >> 2);
        g_w2t[(size_t)k * 4096 + n * 64 + p] = u;
    }
    // W3 [64,256] -> two 128-col B tiles, p2-permuted on k(=c)
    {
        int i = blockIdx.x * 256 + threadIdx.x;   // 64*256 = 16384 exactly
        int c = i >> 8, n = i & 255;
        uint32_t u = to_tf32(W3[i]);
        int p = (c & 48) + ((c & 3) << 2) + ((c & 15) >> 2);
        g_w3t[(n >> 7) * 8192 + (n & 127) * 64 + p] = u;
    }
}

// ---------------- k1b: g_y1t = p2-permute(tf32(relu(bn1(y1)))) --------------
__global__ __launch_bounds__(256) void k1b()
{
    size_t i = (size_t)blockIdx.x * 256 + threadIdx.x;   // float4 index
    if (i >= (size_t)N_NODES * 16) return;
    int c4 = (int)(i & 15), cb = c4 * 4;
    float4 v = *(const float4*)&g_y1[i * 4];
    uint32_t u0 = to_tf32(fmaxf(fmaf(v.x, g_sc1[cb],     g_sh1[cb]),     0.f));
    uint32_t u1 = to_tf32(fmaxf(fmaf(v.y, g_sc1[cb + 1], g_sh1[cb + 1]), 0.f));
    uint32_t u2 = to_tf32(fmaxf(fmaf(v.z, g_sc1[cb + 2], g_sh1[cb + 2]), 0.f));
    uint32_t u3 = to_tf32(fmaxf(fmaf(v.w, g_sc1[cb + 3], g_sh1[cb + 3]), 0.f));
    int base = (cb & 48) + ((cb & 15) >> 2);
    uint32_t* dst = g_y1t + (i >> 4) * 64 + base;
    dst[0] = u0; dst[4] = u1; dst[8] = u2; dst[12] = u3;
}

// ---------------- K2: tf32 mma.sync gather-GEMM (unchanged) -----------------
#define K2_AS   0        // word offsets: A 2 x 128 x 64
#define K2_BS   16384    // B 2 x 64 x 64
#define K2_PS   24576    // 4 x 64
#define K2_PQ   24832    // 4 x 64
#define K2_U32  25088    // 100352 bytes -> 2 CTAs / SM

__device__ __forceinline__ void k2_issue(
    uint32_t sbase, int tid, int grow, int cI0, int gvalid, int gi,
    int k, int buf)
{
    const char* bs = (const char*)(g_w2t + (size_t)k * 4096);
#pragma unroll
    for (int q = 0; q < 4; q++) {
        int e = tid + q * 256, n = e >> 4, cI = e & 15;
        uint32_t dw = K2_BS + buf * 4096 + n * 64 + (((uint32_t)cI * 4) ^ ((n & 1) << 4));
        cp16(sbase + dw * 4, bs + e * 16);
    }
    const char* as = (const char*)(g_y1t + (size_t)gi * 64 + cI0 * 4);
    int ssz = gvalid ? 16 : 0;
    uint32_t rbase = K2_AS + buf * 8192 + grow * 64;
    uint32_t rx = (grow & 1) << 4;
#pragma unroll
    for (int q = 0; q < 8; q++) {
        uint32_t dw = rbase + ((((uint32_t)(cI0 + q)) * 4) ^ rx);
        cp16p(sbase + dw * 4, as + q * 16, ssz);
    }
    asm volatile("cp.async.commit_group;" ::: "memory");
}

__global__ __launch_bounds__(256, 2) void k2_tc(const int* __restrict__ neigh)
{
    extern __shared__ uint32_t dsm[];
    uint32_t sbase = smem_u32(dsm);
    float* psum = (float*)(dsm + K2_PS);
    float* psq  = (float*)(dsm + K2_PQ);

    int tid = threadIdx.x, wid = tid >> 5, lane = tid & 31;
    int g = lane >> 2, t = lane & 3;
    int rg = wid >> 1, cg = wid & 1;
    int bid = blockIdx.x, row0 = bid * 128;
    int nval = N_NODES - row0; if (nval > 128) nval = 128;

    int grow = tid >> 1;
    int cI0  = (tid & 1) * 8;
    int gvalid = grow < nval;
    const int* nrow = neigh + (size_t)(row0 + (gvalid ? grow : 0)) * 27;

    float acc[2][4][4];
#pragma unroll
    for (int i = 0; i < 2; i++)
#pragma unroll
        for (int j = 0; j < 4; j++)
#pragma unroll
            for (int u = 0; u < 4; u++) acc[i][j][u] = 0.f;

    int idx_cur  = gvalid ? nrow[0] : 0;
    int idx_next = gvalid ? nrow[1] : 0;
    k2_issue(sbase, tid, grow, cI0, gvalid, idx_cur, 0, 0);

    int ra0 = rg * 32 + g;
    uint32_t gx = (g & 1) << 4;
    for (int k = 0; k < 27; k++) {
        int buf = k & 1;
        asm volatile("cp.async.wait_group 0;" ::: "memory");
        __syncthreads();
        if (k + 1 < 27) {
            k2_issue(sbase, tid, grow, cI0, gvalid, idx_next, k + 1, buf ^ 1);
            idx_next = (gvalid && k + 2 < 27) ? nrow[k + 2] : 0;
        }
        const uint32_t* As = dsm + K2_AS + buf * 8192;
        const uint32_t* Bs = dsm + K2_BS + buf * 4096;
#pragma unroll
        for (int kkp = 0; kkp < 4; kkp++) {
            uint32_t off = (uint32_t)(kkp * 16 + t * 4) ^ gx;
            uint4 a00 = *(const uint4*)&As[(ra0     ) * 64 + off];
            uint4 a01 = *(const uint4*)&As[(ra0 +  8) * 64 + off];
            uint4 a10 = *(const uint4*)&As[(ra0 + 16) * 64 + off];
            uint4 a11 = *(const uint4*)&As[(ra0 + 24) * 64 + off];
#pragma unroll
            for (int j = 0; j < 4; j++) {
                int nt = cg * 4 + j;
                uint4 b = *(const uint4*)&Bs[(nt * 8 + g) * 64 + off];
                mma_tf32(acc[0][j], a00.x, a01.x, a00.y, a01.y, b.x, b.y);
                mma_tf32(acc[0][j], a00.z, a01.z, a00.w, a01.w, b.z, b.w);
                mma_tf32(acc[1][j], a10.x, a11.x, a10.y, a11.y, b.x, b.y);
                mma_tf32(acc[1][j], a10.z, a11.z, a10.w, a11.w, b.z, b.w);
            }
        }
    }

    int rbase = row0 + rg * 32 + g;
#pragma unroll
    for (int j = 0; j < 4; j++) {
        int col = cg * 32 + j * 8 + t * 2;
        float s0 = 0.f, s1 = 0.f, q0 = 0.f, q1 = 0.f;
#pragma unroll
        for (int i = 0; i < 2; i++) {
            float c0 = acc[i][j][0], c1 = acc[i][j][1];
            float c2 = acc[i][j][2], c3 = acc[i][j][3];
            int rowA = rbase + i * 16, rowB = rowA + 8;
            if (rowA < N_NODES) {
                float2 v; v.x = c0; v.y = c1;
                *(float2*)&g_y2[(size_t)rowA * 64 + col] = v;
            }
            if (rowB < N_NODES) {
                float2 v; v.x = c2; v.y = c3;
                *(float2*)&g_y2[(size_t)rowB * 64 + col] = v;
            }
            s0 += c0 + c2;  s1 += c1 + c3;
            q0 += c0 * c0 + c2 * c2;  q1 += c1 * c1 + c3 * c3;
        }
#pragma unroll
        for (int d = 4; d <= 16; d <<= 1) {
            s0 += __shfl_xor_sync(0xFFFFFFFFu, s0, d);
            s1 += __shfl_xor_sync(0xFFFFFFFFu, s1, d);
            q0 += __shfl_xor_sync(0xFFFFFFFFu, q0, d);
            q1 += __shfl_xor_sync(0xFFFFFFFFu, q1, d);
        }
        if (g == 0) {
            psum[rg * 64 + col]     = s0;
            psum[rg * 64 + col + 1] = s1;
            psq [rg * 64 + col]     = q0;
            psq [rg * 64 + col + 1] = q1;
        }
    }
    __syncthreads();
    if (tid < 64) {
        float s = 0.f, q = 0.f;
#pragma unroll
        for (int w = 0; w < 4; w++) { s += psum[w * 64 + tid]; q += psq[w * 64 + tid]; }
        g_part2[bid * 128 + tid]      = s;
        g_part2[bid * 128 + 64 + tid] = q;
    }
}

__global__ void f2k(const float* g, const float* b) { fin_body(g_part2, NB2, 64, g, b, g_sc2, g_sh2); }

// ---------------- k2b: g_y2t = p2-permute(tf32(relu(bn2(y2)))) --------------
__global__ __launch_bounds__(256) void k2b()
{
    size_t i = (size_t)blockIdx.x * 256 + threadIdx.x;
    if (i >= (size_t)N_NODES * 16) return;
    int c4 = (int)(i & 15), cb = c4 * 4;
    float4 v = *(const float4*)&g_y2[i * 4];
    uint32_t u0 = to_tf32(fmaxf(fmaf(v.x, g_sc2[cb],     g_sh2[cb]),     0.f));
    uint32_t u1 = to_tf32(fmaxf(fmaf(v.y, g_sc2[cb + 1], g_sh2[cb + 1]), 0.f));
    uint32_t u2 = to_tf32(fmaxf(fmaf(v.z, g_sc2[cb + 2], g_sh2[cb + 2]), 0.f));
    uint32_t u3 = to_tf32(fmaxf(fmaf(v.w, g_sc2[cb + 3], g_sh2[cb + 3]), 0.f));
    int base = (cb & 48) + ((cb & 15) >> 2);
    uint32_t* dst = g_y2t + (i >> 4) * 64 + base;
    dst[0] = u0; dst[4] = u1; dst[8] = u2; dst[12] = u3;
}

// ---------------- k3a: partial G = A^T A, m = A^T 1 (a = relu(bn2(y2))) -----
// 32-row tiles: as[32*64] exactly matches the 512-float4 loader.
__global__ __launch_bounds__(256) void k3a()
{
    __shared__ __align__(16) float as[32 * 64];
    int tid = threadIdx.x, b = blockIdx.x;
    int gr0 = b * RPB3;
    int rows = N_NODES - gr0; if (rows > RPB3) rows = RPB3;
    int ti = tid >> 4, tj = tid & 15;

    // loader channel constants (this thread always loads c4 = (tid*2+q)&15)
    int lc0 = ((tid * 2)     & 15) * 4;
    int lc1 = ((tid * 2 + 1) & 15) * 4;
    float4 sc0 = *(const float4*)&g_sc2[lc0], sh0 = *(const float4*)&g_sh2[lc0];
    float4 sc1 = *(const float4*)&g_sc2[lc1], sh1 = *(const float4*)&g_sh2[lc1];

    float cacc[4][4];
#pragma unroll
    for (int u = 0; u < 4; u++)
#pragma unroll
        for (int v = 0; v < 4; v++) cacc[u][v] = 0.f;
    float macc[4] = {0.f, 0.f, 0.f, 0.f};

    for (int r0 = 0; r0 < RPB3; r0 += 32) {
        __syncthreads();
#pragma unroll
        for (int q = 0; q < 2; q++) {
            int f = tid * 2 + q;            // 0..511 = 32 rows x 16 chunks
            int r8 = f >> 4, c4 = f & 15;
            float4 v; v.x = 0.f; v.y = 0.f; v.z = 0.f; v.w = 0.f;
            if (r0 + r8 < rows) {
                float4 y = *(const float4*)&g_y2[(size_t)(gr0 + r0 + r8) * 64 + c4 * 4];
                float4 sc = q ? sc1 : sc0, sh = q ? sh1 : sh0;
                v.x = fmaxf(fmaf(y.x, sc.x, sh.x), 0.f);
                v.y = fmaxf(fmaf(y.y, sc.y, sh.y), 0.f);
                v.z = fmaxf(fmaf(y.z, sc.z, sh.z), 0.f);
                v.w = fmaxf(fmaf(y.w, sc.w, sh.w), 0.f);
            }
            *(float4*)&as[r8 * 64 + c4 * 4] = v;
        }
        __syncthreads();
#pragma unroll
        for (int r = 0; r < 32; r++) {
            float4 ai = *(const float4*)&as[r * 64 + ti * 4];
            float4 aj = *(const float4*)&as[r * 64 + tj * 4];
            cacc[0][0] += ai.x * aj.x; cacc[0][1] += ai.x * aj.y;
            cacc[0][2] += ai.x * aj.z; cacc[0][3] += ai.x * aj.w;
            cacc[1][0] += ai.y * aj.x; cacc[1][1] += ai.y * aj.y;
            cacc[1][2] += ai.y * aj.z; cacc[1][3] += ai.y * aj.w;
            cacc[2][0] += ai.z * aj.x; cacc[2][1] += ai.z * aj.y;
            cacc[2][2] += ai.z * aj.z; cacc[2][3] += ai.z * aj.w;
            cacc[3][0] += ai.w * aj.x; cacc[3][1] += ai.w * aj.y;
            cacc[3][2] += ai.w * aj.z; cacc[3][3] += ai.w * aj.w;
            if (tj == 0) {
                macc[0] += ai.x; macc[1] += ai.y; macc[2] += ai.z; macc[3] += ai.w;
            }
        }
    }
    float* part = g_z + (size_t)b * 4224;
#pragma unroll
    for (int u = 0; u < 4; u++)
#pragma unroll
        for (int v = 0; v < 4; v++)
            part[(ti * 4 + u) * 64 + tj * 4 + v] = cacc[u][v];
    if (tj == 0)
#pragma unroll
        for (int u = 0; u < 4; u++) part[4096 + ti * 4 + u] = macc[u];
}

// ---------------- f3a: reduce k3a partials -> g_cov -------------------------
__global__ __launch_bounds__(256) void f3a()
{
    int e = blockIdx.x * 256 + threadIdx.x;
    if (e >= 4160) return;
    float s = 0.f;
    for (int b = 0; b < CB3; b++) s += g_z[(size_t)b * 4224 + e];
    g_cov[e] = s;
}

// ---------------- f3b: analytic BN3 scales from G, m, W3 --------------------
__global__ __launch_bounds__(64) void f3b(
    const float* __restrict__ W3, const float* __restrict__ g3,
    const float* __restrict__ b3)
{
    __shared__ float Gs[4096];
    __shared__ float sw[64 * 64];
    __shared__ float ma[64];
    int tid = threadIdx.x;
    int c = blockIdx.x * 64 + tid;
    for (int i = tid; i < 4096; i += 64) Gs[i] = g_cov[i];
    ma[tid] = g_cov[4096 + tid] * (1.f / (float)N_NODES);
    for (int j = 0; j < 64; j++) sw[j * 64 + tid] = W3[j * 256 + c];
    __syncthreads();
    float mz = 0.f, acc = 0.f;
    for (int i = 0; i < 64; i++) {
        float wi = sw[i * 64 + tid];
        mz = fmaf(ma[i], wi, mz);
        float si = 0.f;
#pragma unroll 8
        for (int j = 0; j < 64; j++) si = fmaf(Gs[i * 64 + j], sw[j * 64 + tid], si);
        acc = fmaf(wi, si, acc);
    }
    float var = acc * (1.f / (float)N_NODES) - mz * mz;
    float r = rsqrtf(var + EPS_BN);
    float sc = g3[c] * r;
    g_sc3[c] = sc;
    g_sh3[c] = b3[c] - mz * sc;
}

// ---------------- k3b: out = relu(bn3(a @ W3) + x), tf32 mma ----------------
#define K3B_AS   0        // A: 128 x 64 words
#define K3B_BS   8192     // B: 128 x 64 words
#define K3B_U32  16384    // 65536 bytes

__global__ __launch_bounds__(256, 2) void k3b(
    const float* __restrict__ x, float* __restrict__ out)
{
    extern __shared__ uint32_t dsm3[];
    uint32_t sbase = smem_u32(dsm3);
    int tid = threadIdx.x, wid = tid >> 5, lane = tid & 31;
    int g = lane >> 2, t = lane & 3;
    int rg = wid >> 1, cg = wid & 1;
    int row0 = blockIdx.x * 128, cbk = blockIdx.y;
    int nval = N_NODES - row0; if (nval > 128) nval = 128;

    // A fill from g_y2t (sequential rows)
    {
        int grow = tid >> 1, h = (tid & 1) * 8;
        int gv = grow < nval;
        const char* as = (const char*)(g_y2t +
            (size_t)(row0 + (gv ? grow : 0)) * 64 + h * 4);
        int ssz = gv ? 16 : 0;
        uint32_t rbase = K3B_AS + grow * 64;
        uint32_t rx = (grow & 1) << 4;
#pragma unroll
        for (int q = 0; q < 8; q++) {
            uint32_t dw = rbase + ((((uint32_t)(h + q)) * 4) ^ rx);
            cp16p(sbase + dw * 4, as + q * 16, ssz);
        }
    }
    // B fill (W3 col-block cbk): 128 rows x 16 chunks
    {
        const char* bs = (const char*)(g_w3t + cbk * 8192);
#pragma unroll
        for (int q = 0; q < 8; q++) {
            int e = tid + q * 256, n = e >> 4, cI = e & 15;
            uint32_t dw = K3B_BS + n * 64 + (((uint32_t)cI * 4) ^ ((n & 1) << 4));
            cp16(sbase + dw * 4, bs + e * 16);
        }
    }
    asm volatile("cp.async.commit_group;" ::: "memory");
    asm volatile("cp.async.wait_group 0;" ::: "memory");
    __syncthreads();

    float acc[2][8][4];
#pragma unroll
    for (int i = 0; i < 2; i++)
#pragma unroll
        for (int j = 0; j < 8; j++)
#pragma unroll
            for (int u = 0; u < 4; u++) acc[i][j][u] = 0.f;

    int ra0 = rg * 32 + g;
    uint32_t gx = (g & 1) << 4;
    const uint32_t* As = dsm3 + K3B_AS;
    const uint32_t* Bs = dsm3 + K3B_BS;
#pragma unroll
    for (int kkp = 0; kkp < 4; kkp++) {
        uint32_t off = (uint32_t)(kkp * 16 + t * 4) ^ gx;
        uint4 a00 = *(const uint4*)&As[(ra0     ) * 64 + off];
        uint4 a01 = *(const uint4*)&As[(ra0 +  8) * 64 + off];
        uint4 a10 = *(const uint4*)&As[(ra0 + 16) * 64 + off];
        uint4 a11 = *(const uint4*)&As[(ra0 + 24) * 64 + off];
#pragma unroll
        for (int j = 0; j < 8; j++) {
            int n = cg * 64 + j * 8 + g;
            uint4 b = *(const uint4*)&Bs[n * 64 + off];
            mma_tf32(acc[0][j], a00.x, a01.x, a00.y, a01.y, b.x, b.y);
            mma_tf32(acc[0][j], a00.z, a01.z, a00.w, a01.w, b.z, b.w);
            mma_tf32(acc[1][j], a10.x, a11.x, a10.y, a11.y, b.x, b.y);
            mma_tf32(acc[1][j], a10.z, a11.z, a10.w, a11.w, b.z, b.w);
        }
    }

    // epilogue: bn3 + residual + relu -> out
    int rbase = row0 + rg * 32 + g;
#pragma unroll
    for (int j = 0; j < 8; j++) {
        int col = cbk * 128 + cg * 64 + j * 8 + t * 2;
        float sc0 = g_sc3[col],     sh0 = g_sh3[col];
        float sc1 = g_sc3[col + 1], sh1 = g_sh3[col + 1];
#pragma unroll
        for (int i = 0; i < 2; i++) {
            int rowA = rbase + i * 16, rowB = rowA + 8;
            if (rowA < N_NODES) {
                float2 xv = *(const float2*)&x[(size_t)rowA * 256 + col];
                float2 o;
                o.x = fmaxf(fmaf(acc[i][j][0], sc0, sh0) + xv.x, 0.f);
                o.y = fmaxf(fmaf(acc[i][j][1], sc1, sh1) + xv.y, 0.f);
                *(float2*)&out[(size_t)rowA * 256 + col] = o;
            }
            if (rowB < N_NODES) {
                float2 xv = *(const float2*)&x[(size_t)rowB * 256 + col];
                float2 o;
                o.x = fmaxf(fmaf(acc[i][j][2], sc0, sh0) + xv.x, 0.f);
                o.y = fmaxf(fmaf(acc[i][j][3], sc1, sh1) + xv.y, 0.f);
                *(float2*)&out[(size_t)rowB * 256 + col] = o;
            }
        }
    }
}

// ---------------- launch ---------------------------------------------------
extern "C" void kernel_launch(void* const* d_in, const int* in_sizes, int n_in,
                              void* d_out, int out_size)
{
    const float* x     = (const float*)d_in[0];
    const int*   neigh = (const int*)  d_in[1];
    const float* W1 = (const float*)d_in[3];
    const float* g1 = (const float*)d_in[4];
    const float* b1 = (const float*)d_in[5];
    const float* W2 = (const float*)d_in[6];
    const float* g2 = (const float*)d_in[7];
    const float* b2 = (const float*)d_in[8];
    const float* W3 = (const float*)d_in[9];
    const float* g3 = (const float*)d_in[10];
    const float* b3 = (const float*)d_in[11];
    float* out = (float*)d_out;

    cudaFuncSetAttribute(k2_tc, cudaFuncAttributeMaxDynamicSharedMemorySize,
                         K2_U32 * 4);
    cudaFuncSetAttribute(k3b, cudaFuncAttributeMaxDynamicSharedMemorySize,
                         K3B_U32 * 4);

    k1_gemm<<<NB1, 128>>>(x, W1);                        // 1
    f1p<<<64, 256>>>(g1, b1, W2, W3);                    // 2
    k1b<<<(N_NODES * 16 + 255) / 256, 256>>>();          // 3
    k2_tc<<<NB2, 256, K2_U32 * 4>>>(neigh);              // 4 (profiled slot)
    f2k<<<64, 256>>>(g2, b2);                            // 5
    k2b<<<(N_NODES * 16 + 255) / 256, 256>>>();          // 6
    k3a<<<CB3, 256>>>();                                 // 7
    f3a<<<17, 256>>>();                                  // 8
    f3b<<<4, 64>>>(W3, g3, b3);                          // 9
    k3b<<<dim3(NB2, 2), 256, K3B_U32 * 4>>>(x, out);     // 10
}

// round 17
// speedup vs baseline: 1.7289x; 1.0308x over previous
#include <cuda_runtime.h>
#include <cstdint>

#define N_NODES 200000
#define NB2 1563            // 128-row tiles for K1/K2/K3b
#define CB3 1184            // cov blocks
#define RPB3 169            // rows per cov block (1184*169 = 200096)
#define EPS_BN 1e-3f

// ---------------- scratch (device globals; no allocations allowed) ----------
__device__ __align__(16) float    g_y1 [N_NODES * 64];   // x @ W1 (pre-BN)
__device__ __align__(16) uint32_t g_y1t[N_NODES * 64];   // relu(bn1(y1)), tf32, p2-perm
__device__ __align__(16) float    g_y2 [N_NODES * 64];   // conv2 out (pre-BN)
__device__ __align__(16) uint32_t g_y2t[N_NODES * 64];   // relu(bn2(y2)), tf32, p2-perm
__device__ __align__(16) float    g_z  [N_NODES * 256];  // scratch: k3a partials
__device__ float g_part1[NB2 * 128];
__device__ float g_part2[NB2 * 128];
__device__ float g_cov[4160];                            // reduced G (64x64) + m (64)
__device__ float g_sc1[64],  g_sh1[64];
__device__ float g_sc2[64],  g_sh2[64];
__device__ float g_sc3[256], g_sh3[256];
__device__ __align__(16) uint32_t g_w1t[4 * 4096];       // W1^T, tf32, p2-perm, 4 k-tiles
__device__ __align__(16) uint32_t g_w2t[27 * 4096];      // W2^T, tf32, p2-perm
__device__ __align__(16) uint32_t g_w3t[2 * 128 * 64];   // W3^T, tf32, p2-perm, 2 col-blocks

// ---------------- helpers ---------------------------------------------------
__device__ __forceinline__ uint32_t to_tf32(float v) {
    uint32_t u; asm("cvt.rna.tf32.f32 %0, %1;" : "=r"(u) : "f"(v)); return u;
}
__device__ __forceinline__ uint32_t smem_u32(const void* p) {
    uint32_t a; asm("{ .reg .u64 t; cvta.to.shared.u64 t, %1; cvt.u32.u64 %0, t; }"
                    : "=r"(a) : "l"(p));
    return a;
}
__device__ __forceinline__ void mma_tf32(float* c,
    uint32_t a0, uint32_t a1, uint32_t a2, uint32_t a3, uint32_t b0, uint32_t b1)
{
    asm volatile(
        "mma.sync.aligned.m16n8k8.row.col.f32.tf32.tf32.f32 "
        "{%0,%1,%2,%3}, {%4,%5,%6,%7}, {%8,%9}, {%0,%1,%2,%3};"
        : "+f"(c[0]), "+f"(c[1]), "+f"(c[2]), "+f"(c[3])
        : "r"(a0), "r"(a1), "r"(a2), "r"(a3), "r"(b0), "r"(b1));
}
__device__ __forceinline__ void cp16(uint32_t dst, const void* src) {
    asm volatile("cp.async.cg.shared.global [%0], [%1], 16;" :: "r"(dst), "l"(src));
}
__device__ __forceinline__ void cp16p(uint32_t dst, const void* src, int ssz) {
    asm volatile("cp.async.cg.shared.global [%0], [%1], 16, %2;"
                 :: "r"(dst), "l"(src), "r"(ssz));
}

// p2 channel permutation: chans (kk*8+t, kk*8+t+4) of a kk-pair -> one 16B chunk
// p2(c) = (c&48) + 4*(c&3) + ((c&15)>>2)

// ---------------- k0: W1/W2/W3 -> tf32 p2-permuted images -------------------
__global__ __launch_bounds__(256) void k0(
    const float* __restrict__ W1, const float* __restrict__ W2,
    const float* __restrict__ W3)
{
    int idx0 = blockIdx.x * 256 + threadIdx.x;   // 16384 threads
    // W1 [256,64]: tile kc = c>>6
    {
        int i = idx0; int c = i >> 6, n = i & 63;
        int cc = c & 63;
        int p = (cc & 48) + ((cc & 3) << 2) + ((cc & 15) >> 2);
        g_w1t[(c >> 6) * 4096 + n * 64 + p] = to_tf32(W1[i]);
    }
    // W2 [27,64,64]
    for (int i = idx0; i < 27 * 4096; i += 16384) {
        int e = i & 4095;
        int c = e >> 6, n = e & 63;
        int p = (c & 48) + ((c & 3) << 2) + ((c & 15) >> 2);
        g_w2t[(size_t)(i >> 12) * 4096 + n * 64 + p] = to_tf32(W2[i]);
    }
    // W3 [64,256] -> two 128-col tiles
    {
        int i = idx0; int c = i >> 8, n = i & 255;
        int p = (c & 48) + ((c & 3) << 2) + ((c & 15) >> 2);
        g_w3t[(n >> 7) * 8192 + (n & 127) * 64 + p] = to_tf32(W3[i]);
    }
}

// ---------------- BN finalize body ------------------------------------------
__device__ __forceinline__ void fin_body(
    const float* part, int nb, int C, const float* gamma, const float* beta,
    float* sc, float* sh)
{
    __shared__ float ss[256], sq[256];
    int c = blockIdx.x, t = threadIdx.x;
    float s = 0.f, q = 0.f;
    for (int b = t; b < nb; b += 256) {
        s += part[(size_t)b * 2 * C + c];
        q += part[(size_t)b * 2 * C + C + c];
    }
    ss[t] = s; sq[t] = q; __syncthreads();
    for (int d = 128; d; d >>= 1) {
        if (t < d) { ss[t] += ss[t + d]; sq[t] += sq[t + d]; }
        __syncthreads();
    }
    if (t == 0) {
        float mean = ss[0] / (float)N_NODES;
        float var  = sq[0] / (float)N_NODES - mean * mean;
        float r = rsqrtf(var + EPS_BN);
        float scale = gamma[c] * r;
        sc[c] = scale;
        sh[c] = beta[c] - mean * scale;
    }
}
__global__ void f1k(const float* g, const float* b) { fin_body(g_part1, NB2, 64, g, b, g_sc1, g_sh1); }
__global__ void f2k(const float* g, const float* b) { fin_body(g_part2, NB2, 64, g, b, g_sc2, g_sh2); }

// ---------------- shared mma epilogue: store y + stat partials --------------
__device__ __forceinline__ void mma_epilogue_stats(
    float acc[2][4][4], float* ybuf, float* psum, float* psq, float* partout,
    int row0, int rg, int cg, int g, int t, int tid)
{
    int rbase = row0 + rg * 32 + g;
#pragma unroll
    for (int j = 0; j < 4; j++) {
        int col = cg * 32 + j * 8 + t * 2;
        float s0 = 0.f, s1 = 0.f, q0 = 0.f, q1 = 0.f;
#pragma unroll
        for (int i = 0; i < 2; i++) {
            float c0 = acc[i][j][0], c1 = acc[i][j][1];
            float c2 = acc[i][j][2], c3 = acc[i][j][3];
            int rowA = rbase + i * 16, rowB = rowA + 8;
            if (rowA < N_NODES) {
                float2 v; v.x = c0; v.y = c1;
                *(float2*)&ybuf[(size_t)rowA * 64 + col] = v;
            }
            if (rowB < N_NODES) {
                float2 v; v.x = c2; v.y = c3;
                *(float2*)&ybuf[(size_t)rowB * 64 + col] = v;
            }
            s0 += c0 + c2;  s1 += c1 + c3;
            q0 += c0 * c0 + c2 * c2;  q1 += c1 * c1 + c3 * c3;
        }
#pragma unroll
        for (int d = 4; d <= 16; d <<= 1) {
            s0 += __shfl_xor_sync(0xFFFFFFFFu, s0, d);
            s1 += __shfl_xor_sync(0xFFFFFFFFu, s1, d);
            q0 += __shfl_xor_sync(0xFFFFFFFFu, q0, d);
            q1 += __shfl_xor_sync(0xFFFFFFFFu, q1, d);
        }
        if (g == 0) {
            psum[rg * 64 + col]     = s0;
            psum[rg * 64 + col + 1] = s1;
            psq [rg * 64 + col]     = q0;
            psq [rg * 64 + col + 1] = q1;
        }
    }
    __syncthreads();
    if (tid < 64) {
        float s = 0.f, q = 0.f;
#pragma unroll
        for (int w = 0; w < 4; w++) { s += psum[w * 64 + tid]; q += psq[w * 64 + tid]; }
        partout[tid]      = s;
        partout[64 + tid] = q;
    }
}

// ---------------- k1_tc: y1 = x @ W1, tf32 mma, K=256 in 4 chunks -----------
#define K1_AS   0        // A: 128 x 64 words (one chunk)
#define K1_BS   8192     // B: 4 tiles x 64 x 64 words
#define K1_PS   24576
#define K1_PQ   24832
#define K1_U32  25088    // 100352 bytes -> 2 CTAs / SM

__global__ __launch_bounds__(256, 2) void k1_tc(const float* __restrict__ x)
{
    extern __shared__ uint32_t dsm1[];
    uint32_t sbase = smem_u32(dsm1);
    float* psum = (float*)(dsm1 + K1_PS);
    float* psq  = (float*)(dsm1 + K1_PQ);

    int tid = threadIdx.x, wid = tid >> 5, lane = tid & 31;
    int g = lane >> 2, t = lane & 3;
    int rg = wid >> 1, cg = wid & 1;
    int bid = blockIdx.x, row0 = bid * 128;
    int nval = N_NODES - row0; if (nval > 128) nval = 128;

    // B fill: all 4 tiles (16384 words = 4096 chunks), 16 per thread
    {
        const char* bs = (const char*)g_w1t;
#pragma unroll
        for (int q = 0; q < 16; q++) {
            int e = tid + q * 256;                 // chunk index 0..4095
            int tile = e >> 10, r = e & 1023;
            int n = r >> 4, cI = r & 15;
            uint32_t dw = K1_BS + tile * 4096 + n * 64
                        + (((uint32_t)cI * 4) ^ ((n & 1) << 4));
            cp16(sbase + dw * 4, bs + (size_t)e * 16);
        }
        asm volatile("cp.async.commit_group;" ::: "memory");
    }

    int grow = tid >> 1, h = tid & 1;              // row, 32-chan half
    int gvalid = grow < nval;
    const float* xrow = x + (size_t)(row0 + (gvalid ? grow : 0)) * 256 + h * 32;

    float acc[2][4][4];
#pragma unroll
    for (int i = 0; i < 2; i++)
#pragma unroll
        for (int j = 0; j < 4; j++)
#pragma unroll
            for (int u = 0; u < 4; u++) acc[i][j][u] = 0.f;

    int ra0 = rg * 32 + g;
    uint32_t gx = (g & 1) << 4;
    uint32_t rbase = K1_AS + grow * 64;
    uint32_t rx = (grow & 1) << 4;

    for (int kc = 0; kc < 4; kc++) {
        // load + cvt chunk kc (32 chans for this thread)
        uint32_t w[32];
        if (gvalid) {
#pragma unroll
            for (int q = 0; q < 8; q++) {
                float4 v = *(const float4*)(xrow + kc * 64 + q * 4);
                w[q * 4]     = to_tf32(v.x);
                w[q * 4 + 1] = to_tf32(v.y);
                w[q * 4 + 2] = to_tf32(v.z);
                w[q * 4 + 3] = to_tf32(v.w);
            }
        } else {
#pragma unroll
            for (int q = 0; q < 32; q++) w[q] = 0u;
        }
        if (kc == 0) {
            asm volatile("cp.async.wait_group 0;" ::: "memory");  // B ready
        }
        __syncthreads();   // prior compute done reading As
        // permuted STS: per 16-chan group, out[j] = {w[j], w[4+j], w[8+j], w[12+j]}
#pragma unroll
        for (int gi = 0; gi < 2; gi++) {
#pragma unroll
            for (int j = 0; j < 4; j++) {
                uint4 u;
                u.x = w[gi * 16 + j];
                u.y = w[gi * 16 + 4 + j];
                u.z = w[gi * 16 + 8 + j];
                u.w = w[gi * 16 + 12 + j];
                uint32_t cI = (uint32_t)(h * 8 + gi * 4 + j);
                uint32_t dw = rbase + ((cI * 4) ^ rx);
                *(uint4*)&dsm1[dw] = u;
            }
        }
        __syncthreads();
        // compute
        const uint32_t* As = dsm1 + K1_AS;
        const uint32_t* Bs = dsm1 + K1_BS + kc * 4096;
#pragma unroll
        for (int kkp = 0; kkp < 4; kkp++) {
            uint32_t off = (uint32_t)(kkp * 16 + t * 4) ^ gx;
            uint4 a00 = *(const uint4*)&As[(ra0     ) * 64 + off];
            uint4 a01 = *(const uint4*)&As[(ra0 +  8) * 64 + off];
            uint4 a10 = *(const uint4*)&As[(ra0 + 16) * 64 + off];
            uint4 a11 = *(const uint4*)&As[(ra0 + 24) * 64 + off];
#pragma unroll
            for (int j = 0; j < 4; j++) {
                int nt = cg * 4 + j;
                uint4 b = *(const uint4*)&Bs[(nt * 8 + g) * 64 + off];
                mma_tf32(acc[0][j], a00.x, a01.x, a00.y, a01.y, b.x, b.y);
                mma_tf32(acc[0][j], a00.z, a01.z, a00.w, a01.w, b.z, b.w);
                mma_tf32(acc[1][j], a10.x, a11.x, a10.y, a11.y, b.x, b.y);
                mma_tf32(acc[1][j], a10.z, a11.z, a10.w, a11.w, b.z, b.w);
            }
        }
    }
    mma_epilogue_stats(acc, g_y1, psum, psq, g_part1 + bid * 128,
                       row0, rg, cg, g, t, tid);
}

// ---------------- k1b: g_y1t = p2-permute(tf32(relu(bn1(y1)))) --------------
__global__ __launch_bounds__(256) void k1b()
{
    size_t i = (size_t)blockIdx.x * 256 + threadIdx.x;   // float4 index
    if (i >= (size_t)N_NODES * 16) return;
    int c4 = (int)(i & 15), cb = c4 * 4;
    float4 v = *(const float4*)&g_y1[i * 4];
    uint32_t u0 = to_tf32(fmaxf(fmaf(v.x, g_sc1[cb],     g_sh1[cb]),     0.f));
    uint32_t u1 = to_tf32(fmaxf(fmaf(v.y, g_sc1[cb + 1], g_sh1[cb + 1]), 0.f));
    uint32_t u2 = to_tf32(fmaxf(fmaf(v.z, g_sc1[cb + 2], g_sh1[cb + 2]), 0.f));
    uint32_t u3 = to_tf32(fmaxf(fmaf(v.w, g_sc1[cb + 3], g_sh1[cb + 3]), 0.f));
    int base = (cb & 48) + ((cb & 15) >> 2);
    uint32_t* dst = g_y1t + (i >> 4) * 64 + base;
    dst[0] = u0; dst[4] = u1; dst[8] = u2; dst[12] = u3;
}

// ---------------- K2: tf32 mma.sync gather-GEMM (unchanged) -----------------
#define K2_AS   0        // word offsets: A 2 x 128 x 64
#define K2_BS   16384    // B 2 x 64 x 64
#define K2_PS   24576    // 4 x 64
#define K2_PQ   24832    // 4 x 64
#define K2_U32  25088    // 100352 bytes -> 2 CTAs / SM

__device__ __forceinline__ void k2_issue(
    uint32_t sbase, int tid, int grow, int cI0, int gvalid, int gi,
    int k, int buf)
{
    const char* bs = (const char*)(g_w2t + (size_t)k * 4096);
#pragma unroll
    for (int q = 0; q < 4; q++) {
        int e = tid + q * 256, n = e >> 4, cI = e & 15;
        uint32_t dw = K2_BS + buf * 4096 + n * 64 + (((uint32_t)cI * 4) ^ ((n & 1) << 4));
        cp16(sbase + dw * 4, bs + e * 16);
    }
    const char* as = (const char*)(g_y1t + (size_t)gi * 64 + cI0 * 4);
    int ssz = gvalid ? 16 : 0;
    uint32_t rbase = K2_AS + buf * 8192 + grow * 64;
    uint32_t rx = (grow & 1) << 4;
#pragma unroll
    for (int q = 0; q < 8; q++) {
        uint32_t dw = rbase + ((((uint32_t)(cI0 + q)) * 4) ^ rx);
        cp16p(sbase + dw * 4, as + q * 16, ssz);
    }
    asm volatile("cp.async.commit_group;" ::: "memory");
}

__global__ __launch_bounds__(256, 2) void k2_tc(const int* __restrict__ neigh)
{
    extern __shared__ uint32_t dsm[];
    uint32_t sbase = smem_u32(dsm);
    float* psum = (float*)(dsm + K2_PS);
    float* psq  = (float*)(dsm + K2_PQ);

    int tid = threadIdx.x, wid = tid >> 5, lane = tid & 31;
    int g = lane >> 2, t = lane & 3;
    int rg = wid >> 1, cg = wid & 1;
    int bid = blockIdx.x, row0 = bid * 128;
    int nval = N_NODES - row0; if (nval > 128) nval = 128;

    int grow = tid >> 1;
    int cI0  = (tid & 1) * 8;
    int gvalid = grow < nval;
    const int* nrow = neigh + (size_t)(row0 + (gvalid ? grow : 0)) * 27;

    float acc[2][4][4];
#pragma unroll
    for (int i = 0; i < 2; i++)
#pragma unroll
        for (int j = 0; j < 4; j++)
#pragma unroll
            for (int u = 0; u < 4; u++) acc[i][j][u] = 0.f;

    int idx_cur  = gvalid ? nrow[0] : 0;
    int idx_next = gvalid ? nrow[1] : 0;
    k2_issue(sbase, tid, grow, cI0, gvalid, idx_cur, 0, 0);

    int ra0 = rg * 32 + g;
    uint32_t gx = (g & 1) << 4;
    for (int k = 0; k < 27; k++) {
        int buf = k & 1;
        asm volatile("cp.async.wait_group 0;" ::: "memory");
        __syncthreads();
        if (k + 1 < 27) {
            k2_issue(sbase, tid, grow, cI0, gvalid, idx_next, k + 1, buf ^ 1);
            idx_next = (gvalid && k + 2 < 27) ? nrow[k + 2] : 0;
        }
        const uint32_t* As = dsm + K2_AS + buf * 8192;
        const uint32_t* Bs = dsm + K2_BS + buf * 4096;
#pragma unroll
        for (int kkp = 0; kkp < 4; kkp++) {
            uint32_t off = (uint32_t)(kkp * 16 + t * 4) ^ gx;
            uint4 a00 = *(const uint4*)&As[(ra0     ) * 64 + off];
            uint4 a01 = *(const uint4*)&As[(ra0 +  8) * 64 + off];
            uint4 a10 = *(const uint4*)&As[(ra0 + 16) * 64 + off];
            uint4 a11 = *(const uint4*)&As[(ra0 + 24) * 64 + off];
#pragma unroll
            for (int j = 0; j < 4; j++) {
                int nt = cg * 4 + j;
                uint4 b = *(const uint4*)&Bs[(nt * 8 + g) * 64 + off];
                mma_tf32(acc[0][j], a00.x, a01.x, a00.y, a01.y, b.x, b.y);
                mma_tf32(acc[0][j], a00.z, a01.z, a00.w, a01.w, b.z, b.w);
                mma_tf32(acc[1][j], a10.x, a11.x, a10.y, a11.y, b.x, b.y);
                mma_tf32(acc[1][j], a10.z, a11.z, a10.w, a11.w, b.z, b.w);
            }
        }
    }
    mma_epilogue_stats(acc, g_y2, psum, psq, g_part2 + bid * 128,
                       row0, rg, cg, g, t, tid);
}

// ---------------- k2b: g_y2t = p2-permute(tf32(relu(bn2(y2)))) --------------
__global__ __launch_bounds__(256) void k2b()
{
    size_t i = (size_t)blockIdx.x * 256 + threadIdx.x;
    if (i >= (size_t)N_NODES * 16) return;
    int c4 = (int)(i & 15), cb = c4 * 4;
    float4 v = *(const float4*)&g_y2[i * 4];
    uint32_t u0 = to_tf32(fmaxf(fmaf(v.x, g_sc2[cb],     g_sh2[cb]),     0.f));
    uint32_t u1 = to_tf32(fmaxf(fmaf(v.y, g_sc2[cb + 1], g_sh2[cb + 1]), 0.f));
    uint32_t u2 = to_tf32(fmaxf(fmaf(v.z, g_sc2[cb + 2], g_sh2[cb + 2]), 0.f));
    uint32_t u3 = to_tf32(fmaxf(fmaf(v.w, g_sc2[cb + 3], g_sh2[cb + 3]), 0.f));
    int base = (cb & 48) + ((cb & 15) >> 2);
    uint32_t* dst = g_y2t + (i >> 4) * 64 + base;
    dst[0] = u0; dst[4] = u1; dst[8] = u2; dst[12] = u3;
}

// ---------------- k3a: partial G = A^T A, m = A^T 1 (a = relu(bn2(y2))) -----
__global__ __launch_bounds__(256) void k3a()
{
    __shared__ __align__(16) float as[32 * 64];
    int tid = threadIdx.x, b = blockIdx.x;
    int gr0 = b * RPB3;
    int rows = N_NODES - gr0; if (rows > RPB3) rows = RPB3;
    int ti = tid >> 4, tj = tid & 15;

    int lc0 = ((tid * 2)     & 15) * 4;
    int lc1 = ((tid * 2 + 1) & 15) * 4;
    float4 sc0 = *(const float4*)&g_sc2[lc0], sh0 = *(const float4*)&g_sh2[lc0];
    float4 sc1 = *(const float4*)&g_sc2[lc1], sh1 = *(const float4*)&g_sh2[lc1];

    float cacc[4][4];
#pragma unroll
    for (int u = 0; u < 4; u++)
#pragma unroll
        for (int v = 0; v < 4; v++) cacc[u][v] = 0.f;
    float macc[4] = {0.f, 0.f, 0.f, 0.f};

    for (int r0 = 0; r0 < RPB3; r0 += 32) {
        __syncthreads();
#pragma unroll
        for (int q = 0; q < 2; q++) {
            int f = tid * 2 + q;
            int r8 = f >> 4, c4 = f & 15;
            float4 v; v.x = 0.f; v.y = 0.f; v.z = 0.f; v.w = 0.f;
            if (r0 + r8 < rows) {
                float4 y = *(const float4*)&g_y2[(size_t)(gr0 + r0 + r8) * 64 + c4 * 4];
                float4 sc = q ? sc1 : sc0, sh = q ? sh1 : sh0;
                v.x = fmaxf(fmaf(y.x, sc.x, sh.x), 0.f);
                v.y = fmaxf(fmaf(y.y, sc.y, sh.y), 0.f);
                v.z = fmaxf(fmaf(y.z, sc.z, sh.z), 0.f);
                v.w = fmaxf(fmaf(y.w, sc.w, sh.w), 0.f);
            }
            *(float4*)&as[r8 * 64 + c4 * 4] = v;
        }
        __syncthreads();
#pragma unroll
        for (int r = 0; r < 32; r++) {
            float4 ai = *(const float4*)&as[r * 64 + ti * 4];
            float4 aj = *(const float4*)&as[r * 64 + tj * 4];
            cacc[0][0] += ai.x * aj.x; cacc[0][1] += ai.x * aj.y;
            cacc[0][2] += ai.x * aj.z; cacc[0][3] += ai.x * aj.w;
            cacc[1][0] += ai.y * aj.x; cacc[1][1] += ai.y * aj.y;
            cacc[1][2] += ai.y * aj.z; cacc[1][3] += ai.y * aj.w;
            cacc[2][0] += ai.z * aj.x; cacc[2][1] += ai.z * aj.y;
            cacc[2][2] += ai.z * aj.z; cacc[2][3] += ai.z * aj.w;
            cacc[3][0] += ai.w * aj.x; cacc[3][1] += ai.w * aj.y;
            cacc[3][2] += ai.w * aj.z; cacc[3][3] += ai.w * aj.w;
            if (tj == 0) {
                macc[0] += ai.x; macc[1] += ai.y; macc[2] += ai.z; macc[3] += ai.w;
            }
        }
    }
    float* part = g_z + (size_t)b * 4224;
#pragma unroll
    for (int u = 0; u < 4; u++)
#pragma unroll
        for (int v = 0; v < 4; v++)
            part[(ti * 4 + u) * 64 + tj * 4 + v] = cacc[u][v];
    if (tj == 0)
#pragma unroll
        for (int u = 0; u < 4; u++) part[4096 + ti * 4 + u] = macc[u];
}

// ---------------- f3a: reduce k3a partials -> g_cov -------------------------
__global__ __launch_bounds__(256) void f3a()
{
    int e = blockIdx.x * 256 + threadIdx.x;
    if (e >= 4160) return;
    float s = 0.f;
    for (int b = 0; b < CB3; b++) s += g_z[(size_t)b * 4224 + e];
    g_cov[e] = s;
}

// ---------------- f3b: analytic BN3 scales from G, m, W3 --------------------
__global__ __launch_bounds__(64) void f3b(
    const float* __restrict__ W3, const float* __restrict__ g3,
    const float* __restrict__ b3)
{
    __shared__ float Gs[4096];
    __shared__ float sw[64 * 64];
    __shared__ float ma[64];
    int tid = threadIdx.x;
    int c = blockIdx.x * 64 + tid;
    for (int i = tid; i < 4096; i += 64) Gs[i] = g_cov[i];
    ma[tid] = g_cov[4096 + tid] * (1.f / (float)N_NODES);
    for (int j = 0; j < 64; j++) sw[j * 64 + tid] = W3[j * 256 + c];
    __syncthreads();
    float mz = 0.f, acc = 0.f;
    for (int i = 0; i < 64; i++) {
        float wi = sw[i * 64 + tid];
        mz = fmaf(ma[i], wi, mz);
        float si = 0.f;
#pragma unroll 8
        for (int j = 0; j < 64; j++) si = fmaf(Gs[i * 64 + j], sw[j * 64 + tid], si);
        acc = fmaf(wi, si, acc);
    }
    float var = acc * (1.f / (float)N_NODES) - mz * mz;
    float r = rsqrtf(var + EPS_BN);
    float sc = g3[c] * r;
    g_sc3[c] = sc;
    g_sh3[c] = b3[c] - mz * sc;
}

// ---------------- k3b: out = relu(bn3(a @ W3) + x), tf32 mma ----------------
#define K3B_AS   0        // A: 128 x 64 words
#define K3B_BS   8192     // B: 128 x 64 words
#define K3B_U32  16384    // 65536 bytes

__global__ __launch_bounds__(256, 2) void k3b(
    const float* __restrict__ x, float* __restrict__ out)
{
    extern __shared__ uint32_t dsm3[];
    uint32_t sbase = smem_u32(dsm3);
    int tid = threadIdx.x, wid = tid >> 5, lane = tid & 31;
    int g = lane >> 2, t = lane & 3;
    int rg = wid >> 1, cg = wid & 1;
    int row0 = blockIdx.x * 128, cbk = blockIdx.y;
    int nval = N_NODES - row0; if (nval > 128) nval = 128;

    {
        int grow = tid >> 1, h = (tid & 1) * 8;
        int gv = grow < nval;
        const char* as = (const char*)(g_y2t +
            (size_t)(row0 + (gv ? grow : 0)) * 64 + h * 4);
        int ssz = gv ? 16 : 0;
        uint32_t rbase = K3B_AS + grow * 64;
        uint32_t rx = (grow & 1) << 4;
#pragma unroll
        for (int q = 0; q < 8; q++) {
            uint32_t dw = rbase + ((((uint32_t)(h + q)) * 4) ^ rx);
            cp16p(sbase + dw * 4, as + q * 16, ssz);
        }
    }
    {
        const char* bs = (const char*)(g_w3t + cbk * 8192);
#pragma unroll
        for (int q = 0; q < 8; q++) {
            int e = tid + q * 256, n = e >> 4, cI = e & 15;
            uint32_t dw = K3B_BS + n * 64 + (((uint32_t)cI * 4) ^ ((n & 1) << 4));
            cp16(sbase + dw * 4, bs + e * 16);
        }
    }
    asm volatile("cp.async.commit_group;" ::: "memory");
    asm volatile("cp.async.wait_group 0;" ::: "memory");
    __syncthreads();

    float acc[2][8][4];
#pragma unroll
    for (int i = 0; i < 2; i++)
#pragma unroll
        for (int j = 0; j < 8; j++)
#pragma unroll
            for (int u = 0; u < 4; u++) acc[i][j][u] = 0.f;

    int ra0 = rg * 32 + g;
    uint32_t gx = (g & 1) << 4;
    const uint32_t* As = dsm3 + K3B_AS;
    const uint32_t* Bs = dsm3 + K3B_BS;
#pragma unroll
    for (int kkp = 0; kkp < 4; kkp++) {
        uint32_t off = (uint32_t)(kkp * 16 + t * 4) ^ gx;
        uint4 a00 = *(const uint4*)&As[(ra0     ) * 64 + off];
        uint4 a01 = *(const uint4*)&As[(ra0 +  8) * 64 + off];
        uint4 a10 = *(const uint4*)&As[(ra0 + 16) * 64 + off];
        uint4 a11 = *(const uint4*)&As[(ra0 + 24) * 64 + off];
#pragma unroll
        for (int j = 0; j < 8; j++) {
            int n = cg * 64 + j * 8 + g;
            uint4 b = *(const uint4*)&Bs[n * 64 + off];
            mma_tf32(acc[0][j], a00.x, a01.x, a00.y, a01.y, b.x, b.y);
            mma_tf32(acc[0][j], a00.z, a01.z, a00.w, a01.w, b.z, b.w);
            mma_tf32(acc[1][j], a10.x, a11.x, a10.y, a11.y, b.x, b.y);
            mma_tf32(acc[1][j], a10.z, a11.z, a10.w, a11.w, b.z, b.w);
        }
    }

    int rbase = row0 + rg * 32 + g;
#pragma unroll
    for (int j = 0; j < 8; j++) {
        int col = cbk * 128 + cg * 64 + j * 8 + t * 2;
        float sc0 = g_sc3[col],     sh0 = g_sh3[col];
        float sc1 = g_sc3[col + 1], sh1 = g_sh3[col + 1];
#pragma unroll
        for (int i = 0; i < 2; i++) {
            int rowA = rbase + i * 16, rowB = rowA + 8;
            if (rowA < N_NODES) {
                float2 xv = *(const float2*)&x[(size_t)rowA * 256 + col];
                float2 o;
                o.x = fmaxf(fmaf(acc[i][j][0], sc0, sh0) + xv.x, 0.f);
                o.y = fmaxf(fmaf(acc[i][j][1], sc1, sh1) + xv.y, 0.f);
                *(float2*)&out[(size_t)rowA * 256 + col] = o;
            }
            if (rowB < N_NODES) {
                float2 xv = *(const float2*)&x[(size_t)rowB * 256 + col];
                float2 o;
                o.x = fmaxf(fmaf(acc[i][j][2], sc0, sh0) + xv.x, 0.f);
                o.y = fmaxf(fmaf(acc[i][j][3], sc1, sh1) + xv.y, 0.f);
                *(float2*)&out[(size_t)rowB * 256 + col] = o;
            }
        }
    }
}

// ---------------- launch ---------------------------------------------------
extern "C" void kernel_launch(void* const* d_in, const int* in_sizes, int n_in,
                              void* d_out, int out_size)
{
    const float* x     = (const float*)d_in[0];
    const int*   neigh = (const int*)  d_in[1];
    const float* W1 = (const float*)d_in[3];
    const float* g1 = (const float*)d_in[4];
    const float* b1 = (const float*)d_in[5];
    const float* W2 = (const float*)d_in[6];
    const float* g2 = (const float*)d_in[7];
    const float* b2 = (const float*)d_in[8];
    const float* W3 = (const float*)d_in[9];
    const float* g3 = (const float*)d_in[10];
    const float* b3 = (const float*)d_in[11];
    float* out = (float*)d_out;

    cudaFuncSetAttribute(k1_tc, cudaFuncAttributeMaxDynamicSharedMemorySize,
                         K1_U32 * 4);
    cudaFuncSetAttribute(k2_tc, cudaFuncAttributeMaxDynamicSharedMemorySize,
                         K2_U32 * 4);
    cudaFuncSetAttribute(k3b, cudaFuncAttributeMaxDynamicSharedMemorySize,
                         K3B_U32 * 4);

    k0<<<64, 256>>>(W1, W2, W3);                         // 1
    k1_tc<<<NB2, 256, K1_U32 * 4>>>(x);                  // 2
    f1k<<<64, 256>>>(g1, b1);                            // 3
    k1b<<<(N_NODES * 16 + 255) / 256, 256>>>();          // 4
    k2_tc<<<NB2, 256, K2_U32 * 4>>>(neigh);              // 5
    f2k<<<64, 256>>>(g2, b2);                            // 6
    k2b<<<(N_NODES * 16 + 255) / 256, 256>>>();          // 7
    k3a<<<CB3, 256>>>();                                 // 8
    f3a<<<17, 256>>>();                                  // 9
    f3b<<<4, 64>>>(W3, g3, b3);                          // 10
    k3b<<<dim3(NB2, 2), 256, K3B_U32 * 4>>>(x, out);     // 11
}